// round 5
// baseline (speedup 1.0000x reference)
#include <cuda_runtime.h>
#include <cuda_bf16.h>
#include <cstdint>

#define F 128
static const int NN1 = 50000;   // nodes in g
static const int NE1 = 400000;  // edges in g == nodes of line graph
static const int NE2 = 800000;  // edges in line graph
#define MAXN 400000
#define MAXE 800000

// ---------------- scratch (device globals: no cudaMalloc allowed) ----------
__device__ float  g_P[(size_t)MAXN * 512];       // [row][slot(4)][128] fused projections
__device__ float  g_emsg[(size_t)MAXE * F];
__device__ float  g_h[(size_t)MAXN * F];
__device__ int    g_deg[MAXN];
__device__ int    g_starts[MAXN + 1];
__device__ int    g_cursor[MAXN];
__device__ int    g_elist[MAXE];
__device__ int    g_bsum[1024];
__device__ double g_statsE[256];
__device__ double g_statsN[256];
__device__ float  g_scaleE[F], g_shiftE[F], g_scaleN[F], g_shiftN[F];
__device__ __nv_bfloat16 g_Whi[2 * 5 * 16384];   // swizzled bf16 weight images
__device__ __nv_bfloat16 g_Wlo[2 * 5 * 16384];
__device__ float  g_biasR[2 * 5 * 128];

__device__ __forceinline__ float sigm(float v) { return 1.0f / (1.0f + __expf(-v)); }

__device__ __forceinline__ uint32_t smem_to_u32(const void* p) {
    uint32_t a;
    asm("{ .reg .u64 t; cvta.to.shared.u64 t, %1; cvt.u32.u64 %0, t; }"
        : "=r"(a) : "l"(p));
    return a;
}
__device__ __forceinline__ void cp16(uint32_t dst, const void* src) {
    asm volatile("cp.async.cg.shared.global [%0], [%1], 16;"
                 :: "r"(dst), "l"(src));
}
#define CP_COMMIT() asm volatile("cp.async.commit_group;")
#define CP_WAIT0()  asm volatile("cp.async.wait_group 0;")

#define LDSM_X4(r0, r1, r2, r3, a) \
    asm volatile("ldmatrix.sync.aligned.m8n8.x4.shared.b16 {%0,%1,%2,%3}, [%4];" \
                 : "=r"(r0), "=r"(r1), "=r"(r2), "=r"(r3) : "r"(a))
#define LDSM_X2(r0, r1, a) \
    asm volatile("ldmatrix.sync.aligned.m8n8.x2.shared.b16 {%0,%1}, [%2];" \
                 : "=r"(r0), "=r"(r1) : "r"(a))
#define MMA_BF16(d, a0, a1, a2, a3, b0, b1) \
    asm volatile("mma.sync.aligned.m16n8k16.row.col.f32.bf16.bf16.f32 " \
                 "{%0,%1,%2,%3},{%4,%5,%6,%7},{%8,%9},{%0,%1,%2,%3};" \
                 : "+f"((d)[0]), "+f"((d)[1]), "+f"((d)[2]), "+f"((d)[3]) \
                 : "r"(a0), "r"(a1), "r"(a2), "r"(a3), "r"(b0), "r"(b1))

// XOR-swizzled 128x128 bf16 image: row r, col k; 16B chunks xor'ed by (r&7).
__device__ __host__ __forceinline__ uint32_t sw_byte(int r, int k) {
    return (uint32_t)r * 256u + (uint32_t)(((k >> 3) ^ (r & 7)) << 4)
         + (uint32_t)((k & 7) << 1);
}

// ==================== weight prep: fp32 -> bf16 hi/lo swizzled images =======
__global__ void prep_weights(const float* __restrict__ W1, const float* __restrict__ b1,
                             const float* __restrict__ W2, const float* __restrict__ b2,
                             __nv_bfloat16* __restrict__ Whi,
                             __nv_bfloat16* __restrict__ Wlo,
                             float* __restrict__ biasR)
{
    int idx = blockIdx.x * blockDim.x + threadIdx.x;
    if (idx >= 2 * 5 * 16384) return;
    int c = idx / (5 * 16384);
    int rem = idx % (5 * 16384);
    int s = rem / 16384;
    int e = rem & 16383;
    int n = e >> 7, k = e & 127;
    const int map[5] = {0, 1, 3, 4, 2};   // slots: src_gate,dst_gate,src_upd,dst_upd | edge_gate
    const float* W = (c == 0 ? W1 : W2) + (size_t)map[s] * 16384;
    float a = W[n * 128 + k];
    __nv_bfloat16 h = __float2bfloat16(a);
    __nv_bfloat16 l = __float2bfloat16(a - __bfloat162float(h));
    uint32_t off = sw_byte(n, k) >> 1;
    size_t base = (size_t)(c * 5 + s) * 16384;
    Whi[base + off] = h;
    Wlo[base + off] = l;
    if (e < 128) {
        const float* b = (c == 0 ? b1 : b2);
        biasR[(c * 5 + s) * 128 + e] = b[map[s] * 128 + e];
    }
}

// ==================== HMMA GEMM (256 thr, 8 warps, warp tile 64x32) =========
// out[r, s*128+c] = A[r] @ W_s^T + b_s
// edge mode: + P0[ei[r]] + P1[ej[r]], plus inline BN-stats accumulation.
static constexpr int GEMM_SMEM = 197632;   // A 64KB + 2xW 128KB + stats 1KB

__global__ void __launch_bounds__(256, 1) gemm_mma(
    const float* __restrict__ A, int R,
    const __nv_bfloat16* __restrict__ Whi, const __nv_bfloat16* __restrict__ Wlo,
    const float* __restrict__ biasR, int nW,
    float* __restrict__ out, int outStride,
    const int* __restrict__ ei, const int* __restrict__ ej,
    const float* __restrict__ P, double* __restrict__ stats)
{
    extern __shared__ char smem[];
    const uint32_t sb   = smem_to_u32(smem);
    const uint32_t A_HI = sb, A_LO = sb + 32768;
    const uint32_t WB   = sb + 65536;            // 2 buffers x (hi 32KB + lo 32KB)
    float* ssumS = (float*)(smem + 196608);      // [128]
    float* ssqS  = ssumS + 128;                  // [128]
    const int tid = threadIdx.x, lane = tid & 31, wid = tid >> 5;
    const int warpM = wid & 1, warpN = wid >> 1; // warp tile 64m x 32n
    const int rowBase = blockIdx.x * 128;
    const bool EDGE = (ei != nullptr);

    if (EDGE && tid < 128) { ssumS[tid] = 0.f; ssqS[tid] = 0.f; }

    // prefetch W slot 0 (overlaps with A load/convert)
    {
        const float4* sh = (const float4*)Whi;
        const float4* sl = (const float4*)Wlo;
        #pragma unroll
        for (int u = 0; u < 8; u++) {
            int i = tid + u * 256;
            cp16(WB + (uint32_t)i * 16, sh + i);
            cp16(WB + 32768 + (uint32_t)i * 16, sl + i);
        }
        CP_COMMIT();
    }

    // load + split A tile into hi/lo swizzled smem
    #pragma unroll
    for (int u = 0; u < 16; u++) {
        int idx = tid + u * 256;          // 0..4095 float4s
        int r = idx >> 5, q = idx & 31;   // row, k-float4
        float4 a = make_float4(0.f, 0.f, 0.f, 0.f);
        if (rowBase + r < R)
            a = ((const float4*)(A + (size_t)(rowBase + r) * 128))[q];
        __nv_bfloat16 h0 = __float2bfloat16(a.x), h1 = __float2bfloat16(a.y);
        __nv_bfloat16 h2 = __float2bfloat16(a.z), h3 = __float2bfloat16(a.w);
        __nv_bfloat162 hp0 = __nv_bfloat162(h0, h1), hp1 = __nv_bfloat162(h2, h3);
        __nv_bfloat162 lp0 = __nv_bfloat162(
            __float2bfloat16(a.x - __bfloat162float(h0)),
            __float2bfloat16(a.y - __bfloat162float(h1)));
        __nv_bfloat162 lp1 = __nv_bfloat162(
            __float2bfloat16(a.z - __bfloat162float(h2)),
            __float2bfloat16(a.w - __bfloat162float(h3)));
        uint32_t off = (uint32_t)r * 256 + (uint32_t)((((q >> 1)) ^ (r & 7)) << 4)
                     + (uint32_t)((q & 1) << 3);
        uint2 hv, lv;
        hv.x = *(uint32_t*)&hp0; hv.y = *(uint32_t*)&hp1;
        lv.x = *(uint32_t*)&lp0; lv.y = *(uint32_t*)&lp1;
        *(uint2*)(smem + off)         = hv;
        *(uint2*)(smem + 32768 + off) = lv;
    }

    // per-lane ldmatrix address components
    const int gA  = lane >> 3;
    const int rA  = (lane & 7) + ((gA & 1) << 3);
    const int kcA = gA >> 1;
    const int rB  = lane & 7;
    const int kcB = (lane >> 3) & 1;

    float lsum[8], lsq[8];
    #pragma unroll
    for (int i = 0; i < 8; i++) { lsum[i] = 0.f; lsq[i] = 0.f; }

    for (int s = 0; s < nW; s++) {
        const uint32_t wb = WB + (uint32_t)(s & 1) * 65536;
        if (s == 0) { CP_WAIT0(); __syncthreads(); }
        if (s + 1 < nW) {  // prefetch next W into other buffer
            const float4* sh = (const float4*)(Whi + (size_t)(s + 1) * 16384);
            const float4* sl = (const float4*)(Wlo + (size_t)(s + 1) * 16384);
            uint32_t dst = WB + (uint32_t)((s + 1) & 1) * 65536;
            #pragma unroll
            for (int u = 0; u < 8; u++) {
                int i = tid + u * 256;
                cp16(dst + (uint32_t)i * 16, sh + i);
                cp16(dst + 32768 + (uint32_t)i * 16, sl + i);
            }
            CP_COMMIT();
        }

        float acc[4][4][4];
        #pragma unroll
        for (int mt = 0; mt < 4; mt++)
            #pragma unroll
            for (int nt = 0; nt < 4; nt++)
                #pragma unroll
                for (int i = 0; i < 4; i++) acc[mt][nt][i] = 0.f;

        #pragma unroll
        for (int ks = 0; ks < 8; ks++) {
            uint32_t ah[4][4], al[4][4], bh[4][2], bl[4][2];
            #pragma unroll
            for (int mt = 0; mt < 4; mt++) {
                int row = warpM * 64 + mt * 16 + rA;
                int kc  = ks * 2 + kcA;
                uint32_t off = (uint32_t)row * 256 + (uint32_t)((kc ^ (row & 7)) << 4);
                LDSM_X4(ah[mt][0], ah[mt][1], ah[mt][2], ah[mt][3], A_HI + off);
                LDSM_X4(al[mt][0], al[mt][1], al[mt][2], al[mt][3], A_LO + off);
            }
            #pragma unroll
            for (int nt = 0; nt < 4; nt++) {
                int row = warpN * 32 + nt * 8 + rB;
                int kc  = ks * 2 + kcB;
                uint32_t off = (uint32_t)row * 256 + (uint32_t)((kc ^ (row & 7)) << 4);
                LDSM_X2(bh[nt][0], bh[nt][1], wb + off);
                LDSM_X2(bl[nt][0], bl[nt][1], wb + 32768 + off);
            }
            #pragma unroll
            for (int mt = 0; mt < 4; mt++)
                #pragma unroll
                for (int nt = 0; nt < 4; nt++) {
                    MMA_BF16(acc[mt][nt], ah[mt][0], ah[mt][1], ah[mt][2], ah[mt][3],
                             bh[nt][0], bh[nt][1]);
                    MMA_BF16(acc[mt][nt], ah[mt][0], ah[mt][1], ah[mt][2], ah[mt][3],
                             bl[nt][0], bl[nt][1]);
                    MMA_BF16(acc[mt][nt], al[mt][0], al[mt][1], al[mt][2], al[mt][3],
                             bh[nt][0], bh[nt][1]);
                }
        }

        // epilogue: bias (+ fused P0/P1 gather-add + stats in edge mode) + store
        #pragma unroll
        for (int mt = 0; mt < 4; mt++) {
            int r0 = rowBase + warpM * 64 + mt * 16 + (lane >> 2);
            int r1 = r0 + 8;
            int iA = 0, jA = 0, iB = 0, jB = 0;
            if (EDGE) {
                if (r0 < R) { iA = ei[r0]; jA = ej[r0]; }
                if (r1 < R) { iB = ei[r1]; jB = ej[r1]; }
            }
            #pragma unroll
            for (int nt = 0; nt < 4; nt++) {
                int c = warpN * 32 + nt * 8 + ((lane & 3) << 1);
                float bx = __ldg(biasR + s * 128 + c);
                float by = __ldg(biasR + s * 128 + c + 1);
                if (r0 < R) {
                    float2 v = make_float2(acc[mt][nt][0] + bx, acc[mt][nt][1] + by);
                    if (EDGE) {
                        float2 p0 = *(const float2*)(P + (size_t)iA * 512 + c);
                        float2 p1 = *(const float2*)(P + (size_t)jA * 512 + 128 + c);
                        v.x += p0.x + p1.x; v.y += p0.y + p1.y;
                        lsum[nt * 2]     += v.x; lsq[nt * 2]     += v.x * v.x;
                        lsum[nt * 2 + 1] += v.y; lsq[nt * 2 + 1] += v.y * v.y;
                    }
                    *(float2*)(out + (size_t)r0 * outStride + s * 128 + c) = v;
                }
                if (r1 < R) {
                    float2 v = make_float2(acc[mt][nt][2] + bx, acc[mt][nt][3] + by);
                    if (EDGE) {
                        float2 p0 = *(const float2*)(P + (size_t)iB * 512 + c);
                        float2 p1 = *(const float2*)(P + (size_t)jB * 512 + 128 + c);
                        v.x += p0.x + p1.x; v.y += p0.y + p1.y;
                        lsum[nt * 2]     += v.x; lsq[nt * 2]     += v.x * v.x;
                        lsum[nt * 2 + 1] += v.y; lsq[nt * 2 + 1] += v.y * v.y;
                    }
                    *(float2*)(out + (size_t)r1 * outStride + s * 128 + c) = v;
                }
            }
        }
        if (s + 1 < nW) { CP_WAIT0(); __syncthreads(); }
    }

    if (EDGE) {
        __syncthreads();
        #pragma unroll
        for (int nt = 0; nt < 4; nt++) {
            int c = warpN * 32 + nt * 8 + ((lane & 3) << 1);
            atomicAdd(&ssumS[c],     lsum[nt * 2]);
            atomicAdd(&ssumS[c + 1], lsum[nt * 2 + 1]);
            atomicAdd(&ssqS[c],      lsq[nt * 2]);
            atomicAdd(&ssqS[c + 1],  lsq[nt * 2 + 1]);
        }
        __syncthreads();
        if (tid < 128) {
            atomicAdd(&stats[tid],       (double)ssumS[tid]);
            atomicAdd(&stats[128 + tid], (double)ssqS[tid]);
        }
    }
}

// ---------------- CSR build ------------------------------------------------
__global__ void hist_deg(const int* __restrict__ ei, int* __restrict__ deg, int E)
{
    for (int e = blockIdx.x * blockDim.x + threadIdx.x; e < E;
         e += gridDim.x * blockDim.x)
        atomicAdd(&deg[ei[e]], 1);
}

__global__ void scan1(const int* __restrict__ in, int* __restrict__ out,
                      int* __restrict__ bsum, int n)
{
    __shared__ int s[1024];
    int i = blockIdx.x * 1024 + threadIdx.x;
    int v = (i < n) ? in[i] : 0;
    s[threadIdx.x] = v;
    __syncthreads();
    for (int off = 1; off < 1024; off <<= 1) {
        int t = (threadIdx.x >= off) ? s[threadIdx.x - off] : 0;
        __syncthreads();
        s[threadIdx.x] += t;
        __syncthreads();
    }
    if (i < n) out[i] = s[threadIdx.x] - v;
    if (threadIdx.x == 1023) bsum[blockIdx.x] = s[1023];
}

__global__ void scan2(int* __restrict__ bsum, int nb)
{
    __shared__ int s[1024];
    int v = (threadIdx.x < nb) ? bsum[threadIdx.x] : 0;
    s[threadIdx.x] = v;
    __syncthreads();
    for (int off = 1; off < 1024; off <<= 1) {
        int t = (threadIdx.x >= off) ? s[threadIdx.x - off] : 0;
        __syncthreads();
        s[threadIdx.x] += t;
        __syncthreads();
    }
    if (threadIdx.x < nb) bsum[threadIdx.x] = s[threadIdx.x] - v;
}

__global__ void scan3(int* __restrict__ out, const int* __restrict__ bsum,
                      int n, int total)
{
    int i = blockIdx.x * 1024 + threadIdx.x;
    if (i < n) out[i] += bsum[blockIdx.x];
    if (blockIdx.x == 0 && threadIdx.x == 0) out[n] = total;
}

__global__ void scatter_edges(const int* __restrict__ ei,
                              const int* __restrict__ starts,
                              int* __restrict__ cursor, int* __restrict__ elist, int E)
{
    for (int e = blockIdx.x * blockDim.x + threadIdx.x; e < E;
         e += gridDim.x * blockDim.x) {
        int n = ei[e];
        int p = atomicAdd(&cursor[n], 1);
        elist[starts[n] + p] = e;
    }
}

// ------- per-node aggregation + fused edge BN/silu/residual -----------------
__global__ void __launch_bounds__(256) node_agg(
    const int* __restrict__ starts, const int* __restrict__ elist,
    const int* __restrict__ ej, const float* __restrict__ emsg,
    const float* __restrict__ P,
    float* __restrict__ h, int nN, double* __restrict__ stats,
    const float* __restrict__ scaleE, const float* __restrict__ shiftE,
    const float* __restrict__ eres, float* __restrict__ eout)
{
    __shared__ float ssum[128], ssq[128];
    if (threadIdx.x < 128) { ssum[threadIdx.x] = 0.f; ssq[threadIdx.x] = 0.f; }
    __syncthreads();
    const int lane  = threadIdx.x & 31;
    const int warp  = (blockIdx.x * blockDim.x + threadIdx.x) >> 5;
    const int nwarp = (gridDim.x * blockDim.x) >> 5;
    const float4 scE = ((const float4*)scaleE)[lane];
    const float4 shE = ((const float4*)shiftE)[lane];
    float4 ls = make_float4(0.f, 0.f, 0.f, 0.f);
    float4 lq = make_float4(0.f, 0.f, 0.f, 0.f);
    for (int n = warp; n < nN; n += nwarp) {
        int s = starts[n], t = starts[n + 1];
        float4 sg = make_float4(0.f, 0.f, 0.f, 0.f);
        float4 sn = make_float4(0.f, 0.f, 0.f, 0.f);
        for (int k = s; k < t; k++) {
            int e = elist[k];
            int j = ej[e];
            float4 v  = ((const float4*)emsg)[(long long)e * 32 + lane];
            float4 sig = make_float4(sigm(v.x), sigm(v.y), sigm(v.z), sigm(v.w));
            float4 p4 = ((const float4*)P)[(long long)j * 128 + 96 + lane];
            sg.x += sig.x; sg.y += sig.y; sg.z += sig.z; sg.w += sig.w;
            sn.x += sig.x * p4.x; sn.y += sig.y * p4.y;
            sn.z += sig.z * p4.z; sn.w += sig.w * p4.w;
            // fused edge update: eout = silu(bn(v)) + eres
            float4 b = make_float4(v.x * scE.x + shE.x, v.y * scE.y + shE.y,
                                   v.z * scE.z + shE.z, v.w * scE.w + shE.w);
            float4 er = ((const float4*)eres)[(long long)e * 32 + lane];
            float4 eo = make_float4(b.x * sigm(b.x) + er.x, b.y * sigm(b.y) + er.y,
                                    b.z * sigm(b.z) + er.z, b.w * sigm(b.w) + er.w);
            ((float4*)eout)[(long long)e * 32 + lane] = eo;
        }
        float4 hv = ((const float4*)P)[(long long)n * 128 + 64 + lane];
        hv.x += sn.x / (sg.x + 1e-9f); hv.y += sn.y / (sg.y + 1e-9f);
        hv.z += sn.z / (sg.z + 1e-9f); hv.w += sn.w / (sg.w + 1e-9f);
        ((float4*)h)[(long long)n * 32 + lane] = hv;
        ls.x += hv.x; ls.y += hv.y; ls.z += hv.z; ls.w += hv.w;
        lq.x += hv.x * hv.x; lq.y += hv.y * hv.y;
        lq.z += hv.z * hv.z; lq.w += hv.w * hv.w;
    }
    atomicAdd(&ssum[lane * 4 + 0], ls.x); atomicAdd(&ssum[lane * 4 + 1], ls.y);
    atomicAdd(&ssum[lane * 4 + 2], ls.z); atomicAdd(&ssum[lane * 4 + 3], ls.w);
    atomicAdd(&ssq[lane * 4 + 0], lq.x);  atomicAdd(&ssq[lane * 4 + 1], lq.y);
    atomicAdd(&ssq[lane * 4 + 2], lq.z);  atomicAdd(&ssq[lane * 4 + 3], lq.w);
    __syncthreads();
    if (threadIdx.x < 128) {
        atomicAdd(&stats[threadIdx.x],       (double)ssum[threadIdx.x]);
        atomicAdd(&stats[128 + threadIdx.x], (double)ssq[threadIdx.x]);
    }
}

// ---------------- BN finalize + fused apply ---------------------------------
__global__ void finalize_bn(const double* __restrict__ stats,
                            const float* __restrict__ gamma,
                            const float* __restrict__ beta,
                            double invR, float* __restrict__ scale,
                            float* __restrict__ shift)
{
    int f = threadIdx.x;
    double mu  = stats[f] * invR;
    double var = stats[128 + f] * invR - mu * mu;
    float inv = rsqrtf((float)var + 1e-5f);
    float s = gamma[f] * inv;
    scale[f] = s;
    shift[f] = beta[f] - s * (float)mu;
}

__global__ void apply_bn_silu_res(const float* __restrict__ hbuf,
                                  const float* __restrict__ res,
                                  const float* __restrict__ scale,
                                  const float* __restrict__ shift,
                                  float* __restrict__ out, long long n4)
{
    for (long long idx = (long long)blockIdx.x * blockDim.x + threadIdx.x;
         idx < n4; idx += (long long)gridDim.x * blockDim.x) {
        int l = (int)(idx & 31);
        float4 sc = ((const float4*)scale)[l];
        float4 sh = ((const float4*)shift)[l];
        float4 v = ((const float4*)hbuf)[idx];
        v.x = v.x * sc.x + sh.x; v.y = v.y * sc.y + sh.y;
        v.z = v.z * sc.z + sh.z; v.w = v.w * sc.w + sh.w;
        float4 u = make_float4(v.x * sigm(v.x), v.y * sigm(v.y),
                               v.z * sigm(v.z), v.w * sigm(v.w));
        float4 r = ((const float4*)res)[idx];
        u.x += r.x; u.y += r.y; u.z += r.z; u.w += r.w;
        ((float4*)out)[idx] = u;
    }
}

// ---------------- host orchestration ----------------------------------------
struct Scratch {
    float *P, *emsg, *h;
    int *deg, *starts, *cursor, *elist, *bsum;
    double *statsE, *statsN;
    float *scaleE, *shiftE, *scaleN, *shiftN;
    __nv_bfloat16 *Whi, *Wlo;
    float *biasR;
};

static void run_conv(const Scratch& S, int conv,
                     const int* ei, const int* ej, int nN, int E,
                     const float* xnode, const float* eedge,
                     const float* bng, const float* bnb,
                     const float* node_res, float* node_out,
                     const float* edge_res, float* edge_out)
{
    cudaStream_t st = 0;
    cudaMemsetAsync(S.deg, 0, (size_t)nN * sizeof(int), st);
    cudaMemsetAsync(S.cursor, 0, (size_t)nN * sizeof(int), st);
    cudaMemsetAsync(S.statsE, 0, 256 * sizeof(double), st);
    cudaMemsetAsync(S.statsN, 0, 256 * sizeof(double), st);

    int gbN = (nN + 127) / 128;
    int gbE = (E + 127) / 128;
    const __nv_bfloat16* Whi = S.Whi + (size_t)conv * 5 * 16384;
    const __nv_bfloat16* Wlo = S.Wlo + (size_t)conv * 5 * 16384;
    const float* biasR = S.biasR + conv * 5 * 128;

    // CSR build (independent of GEMMs)
    hist_deg<<<2048, 256, 0, st>>>(ei, S.deg, E);
    int nb = (nN + 1023) / 1024;
    scan1<<<nb, 1024, 0, st>>>(S.deg, S.starts, S.bsum, nN);
    scan2<<<1, 1024, 0, st>>>(S.bsum, nb);
    scan3<<<nb, 1024, 0, st>>>(S.starts, S.bsum, nN, E);
    scatter_edges<<<2048, 256, 0, st>>>(ei, S.starts, S.cursor, S.elist, E);

    // fused node projections (slots 0..3 -> P)
    gemm_mma<<<gbN, 256, GEMM_SMEM, st>>>(xnode, nN, Whi, Wlo, biasR, 4,
                                          S.P, 512, nullptr, nullptr, nullptr,
                                          nullptr);
    // edge projection + fused P0[i]+P1[j] gather-add + inline BN stats -> emsg
    gemm_mma<<<gbE, 256, GEMM_SMEM, st>>>(eedge, E, Whi + 4 * 16384, Wlo + 4 * 16384,
                                          biasR + 4 * 128, 1, S.emsg, 128,
                                          ei, ej, S.P, S.statsE);
    finalize_bn<<<1, 128, 0, st>>>(S.statsE, bng + 0 * 128, bnb + 0 * 128,
                                   1.0 / (double)E, S.scaleE, S.shiftE);

    // node aggregation + node BN stats + fused edge BN/silu/residual output
    node_agg<<<4096, 256, 0, st>>>(S.starts, S.elist, ej, S.emsg, S.P,
                                   S.h, nN, S.statsN,
                                   S.scaleE, S.shiftE, edge_res, edge_out);
    finalize_bn<<<1, 128, 0, st>>>(S.statsN, bng + 1 * 128, bnb + 1 * 128,
                                   1.0 / (double)nN, S.scaleN, S.shiftN);

    long long n4n = (long long)nN * 32;
    int gbA = (int)((n4n + 255) / 256); if (gbA > 8192) gbA = 8192;
    apply_bn_silu_res<<<gbA, 256, 0, st>>>(S.h, node_res, S.scaleN, S.shiftN,
                                           node_out, n4n);
}

extern "C" void kernel_launch(void* const* d_in, const int* in_sizes, int n_in,
                              void* d_out, int out_size)
{
    const int*   gidx = (const int*)d_in[0];
    const int*   lidx = (const int*)d_in[1];
    const float* x    = (const float*)d_in[2];
    const float* y    = (const float*)d_in[3];
    const float* z    = (const float*)d_in[4];
    const float* W1   = (const float*)d_in[5];
    const float* b1   = (const float*)d_in[6];
    const float* bng1 = (const float*)d_in[7];
    const float* bnb1 = (const float*)d_in[8];
    const float* W2   = (const float*)d_in[9];
    const float* b2   = (const float*)d_in[10];
    const float* bng2 = (const float*)d_in[11];
    const float* bnb2 = (const float*)d_in[12];

    float* xo = (float*)d_out;
    float* yo = xo + (long long)NN1 * F;
    float* zo = yo + (long long)NE1 * F;

    Scratch S;
    cudaGetSymbolAddress((void**)&S.P, g_P);
    cudaGetSymbolAddress((void**)&S.emsg, g_emsg);
    cudaGetSymbolAddress((void**)&S.h, g_h);
    cudaGetSymbolAddress((void**)&S.deg, g_deg);
    cudaGetSymbolAddress((void**)&S.starts, g_starts);
    cudaGetSymbolAddress((void**)&S.cursor, g_cursor);
    cudaGetSymbolAddress((void**)&S.elist, g_elist);
    cudaGetSymbolAddress((void**)&S.bsum, g_bsum);
    cudaGetSymbolAddress((void**)&S.statsE, g_statsE);
    cudaGetSymbolAddress((void**)&S.statsN, g_statsN);
    cudaGetSymbolAddress((void**)&S.scaleE, g_scaleE);
    cudaGetSymbolAddress((void**)&S.shiftE, g_shiftE);
    cudaGetSymbolAddress((void**)&S.scaleN, g_scaleN);
    cudaGetSymbolAddress((void**)&S.shiftN, g_shiftN);
    cudaGetSymbolAddress((void**)&S.Whi, g_Whi);
    cudaGetSymbolAddress((void**)&S.Wlo, g_Wlo);
    cudaGetSymbolAddress((void**)&S.biasR, g_biasR);

    cudaFuncSetAttribute(gemm_mma, cudaFuncAttributeMaxDynamicSharedMemorySize,
                         GEMM_SMEM);

    prep_weights<<<(2 * 5 * 16384 + 255) / 256, 256>>>(W1, b1, W2, b2,
                                                       S.Whi, S.Wlo, S.biasR);

    // conv1: node_update on g
    run_conv(S, 0, gidx, gidx + NE1, NN1, NE1, x, y, bng1, bnb1,
             /*node_res=*/x, /*node_out=*/xo, /*edge_res=*/y, /*edge_out=*/yo);
    // conv2: edge_update on line graph (nodes = m = yo, edges = z)
    run_conv(S, 1, lidx, lidx + NE2, NE1, NE2, yo, z, bng2, bnb2,
             /*node_res=*/yo, /*node_out=*/yo, /*edge_res=*/z, /*edge_out=*/zo);
}

// round 6
// speedup vs baseline: 1.5620x; 1.5620x over previous
#include <cuda_runtime.h>
#include <cuda_bf16.h>
#include <cstdint>

#define F 128
static const int NN1 = 50000;   // nodes in g
static const int NE1 = 400000;  // edges in g == nodes of line graph
static const int NE2 = 800000;  // edges in line graph
#define MAXN 400000
#define MAXE 800000

// ---------------- scratch (device globals: no cudaMalloc allowed) ----------
__device__ float  g_P[(size_t)MAXN * 512];       // [row][slot(4)][128] fused projections
__device__ float  g_emsg[(size_t)MAXE * F];
__device__ float  g_h[(size_t)MAXN * F];
__device__ int    g_deg[MAXN];
__device__ int    g_starts[MAXN + 1];
__device__ int    g_cursor[MAXN];
__device__ int    g_elist[MAXE];
__device__ int    g_bsum[1024];
__device__ double g_statsE[256];
__device__ double g_statsN[256];
__device__ float  g_scaleE[F], g_shiftE[F], g_scaleN[F], g_shiftN[F];
__device__ __nv_bfloat16 g_Whi[2 * 5 * 16384];   // swizzled bf16 weight images
__device__ __nv_bfloat16 g_Wlo[2 * 5 * 16384];
__device__ float  g_biasR[2 * 5 * 128];

__device__ __forceinline__ float sigm(float v) { return 1.0f / (1.0f + __expf(-v)); }

__device__ __forceinline__ uint32_t smem_to_u32(const void* p) {
    uint32_t a;
    asm("{ .reg .u64 t; cvta.to.shared.u64 t, %1; cvt.u32.u64 %0, t; }"
        : "=r"(a) : "l"(p));
    return a;
}
__device__ __forceinline__ void cp16(uint32_t dst, const void* src) {
    asm volatile("cp.async.cg.shared.global [%0], [%1], 16;"
                 :: "r"(dst), "l"(src));
}
#define CP_COMMIT() asm volatile("cp.async.commit_group;")
#define CP_WAIT0()  asm volatile("cp.async.wait_group 0;")

#define LDSM_X4(r0, r1, r2, r3, a) \
    asm volatile("ldmatrix.sync.aligned.m8n8.x4.shared.b16 {%0,%1,%2,%3}, [%4];" \
                 : "=r"(r0), "=r"(r1), "=r"(r2), "=r"(r3) : "r"(a))
#define LDSM_X2(r0, r1, a) \
    asm volatile("ldmatrix.sync.aligned.m8n8.x2.shared.b16 {%0,%1}, [%2];" \
                 : "=r"(r0), "=r"(r1) : "r"(a))
#define MMA_BF16(d, a0, a1, a2, a3, b0, b1) \
    asm volatile("mma.sync.aligned.m16n8k16.row.col.f32.bf16.bf16.f32 " \
                 "{%0,%1,%2,%3},{%4,%5,%6,%7},{%8,%9},{%0,%1,%2,%3};" \
                 : "+f"((d)[0]), "+f"((d)[1]), "+f"((d)[2]), "+f"((d)[3]) \
                 : "r"(a0), "r"(a1), "r"(a2), "r"(a3), "r"(b0), "r"(b1))

// XOR-swizzled bf16 image: row r (256B row), col k; 16B chunks xor'ed by (r&7).
__device__ __host__ __forceinline__ uint32_t sw_byte(int r, int k) {
    return (uint32_t)r * 256u + (uint32_t)(((k >> 3) ^ (r & 7)) << 4)
         + (uint32_t)((k & 7) << 1);
}

// ==================== weight prep: fp32 -> bf16 hi/lo swizzled images =======
__global__ void prep_weights(const float* __restrict__ W1, const float* __restrict__ b1,
                             const float* __restrict__ W2, const float* __restrict__ b2,
                             __nv_bfloat16* __restrict__ Whi,
                             __nv_bfloat16* __restrict__ Wlo,
                             float* __restrict__ biasR)
{
    int idx = blockIdx.x * blockDim.x + threadIdx.x;
    if (idx >= 2 * 5 * 16384) return;
    int c = idx / (5 * 16384);
    int rem = idx % (5 * 16384);
    int s = rem / 16384;
    int e = rem & 16383;
    int n = e >> 7, k = e & 127;
    const int map[5] = {0, 1, 3, 4, 2};   // slots: src_gate,dst_gate,src_upd,dst_upd | edge_gate
    const float* W = (c == 0 ? W1 : W2) + (size_t)map[s] * 16384;
    float a = W[n * 128 + k];
    __nv_bfloat16 h = __float2bfloat16(a);
    __nv_bfloat16 l = __float2bfloat16(a - __bfloat162float(h));
    uint32_t off = sw_byte(n, k) >> 1;
    size_t base = (size_t)(c * 5 + s) * 16384;
    Whi[base + off] = h;
    Wlo[base + off] = l;
    if (e < 128) {
        const float* b = (c == 0 ? b1 : b2);
        biasR[(c * 5 + s) * 128 + e] = b[map[s] * 128 + e];
    }
}

// ==================== HMMA GEMM (256 thr, 8 warps, M=64 tile, 2 CTAs/SM) ====
// out[r, s*128+c] = A[r] @ W_s^T + b_s.  Warp tile 32m x 32n (2x4 grid).
// smem: A hi/lo 32KB + W hi/lo 64KB = 96KB -> 2 CTAs per SM.
static constexpr int GEMM_SMEM = 98304;

__global__ void __launch_bounds__(256, 2) gemm_mma(
    const float* __restrict__ A, int R,
    const __nv_bfloat16* __restrict__ Whi, const __nv_bfloat16* __restrict__ Wlo,
    const float* __restrict__ biasR, int nW,
    float* __restrict__ out, int outStride)
{
    extern __shared__ char smem[];
    const uint32_t sb   = smem_to_u32(smem);
    const uint32_t A_HI = sb, A_LO = sb + 16384;
    const uint32_t W_HI = sb + 32768, W_LO = sb + 65536;
    const int tid = threadIdx.x, lane = tid & 31, wid = tid >> 5;
    const int warpM = wid & 1, warpN = wid >> 1; // warp tile 32m x 32n
    const int rowBase = blockIdx.x * 64;

    // prefetch W slot 0 (overlaps with A load/convert)
    {
        const float4* sh = (const float4*)Whi;
        const float4* sl = (const float4*)Wlo;
        #pragma unroll
        for (int u = 0; u < 8; u++) {
            int i = tid + u * 256;
            cp16(W_HI + (uint32_t)i * 16, sh + i);
            cp16(W_LO + (uint32_t)i * 16, sl + i);
        }
        CP_COMMIT();
    }

    // load + split A tile (64 rows) into hi/lo swizzled smem
    #pragma unroll
    for (int u = 0; u < 8; u++) {
        int idx = tid + u * 256;          // 0..2047 float4s
        int r = idx >> 5, q = idx & 31;   // row (0..63), k-float4
        float4 a = make_float4(0.f, 0.f, 0.f, 0.f);
        if (rowBase + r < R)
            a = ((const float4*)(A + (size_t)(rowBase + r) * 128))[q];
        __nv_bfloat16 h0 = __float2bfloat16(a.x), h1 = __float2bfloat16(a.y);
        __nv_bfloat16 h2 = __float2bfloat16(a.z), h3 = __float2bfloat16(a.w);
        __nv_bfloat162 hp0 = __nv_bfloat162(h0, h1), hp1 = __nv_bfloat162(h2, h3);
        __nv_bfloat162 lp0 = __nv_bfloat162(
            __float2bfloat16(a.x - __bfloat162float(h0)),
            __float2bfloat16(a.y - __bfloat162float(h1)));
        __nv_bfloat162 lp1 = __nv_bfloat162(
            __float2bfloat16(a.z - __bfloat162float(h2)),
            __float2bfloat16(a.w - __bfloat162float(h3)));
        uint32_t off = (uint32_t)r * 256 + (uint32_t)((((q >> 1)) ^ (r & 7)) << 4)
                     + (uint32_t)((q & 1) << 3);
        uint2 hv, lv;
        hv.x = *(uint32_t*)&hp0; hv.y = *(uint32_t*)&hp1;
        lv.x = *(uint32_t*)&lp0; lv.y = *(uint32_t*)&lp1;
        *(uint2*)(smem + off)         = hv;
        *(uint2*)(smem + 16384 + off) = lv;
    }

    // per-lane ldmatrix address components
    const int gA  = lane >> 3;
    const int rA  = (lane & 7) + ((gA & 1) << 3);
    const int kcA = gA >> 1;
    const int rB  = lane & 7;
    const int kcB = (lane >> 3) & 1;

    for (int s = 0; s < nW; s++) {
        if (s > 0) {
            // single-buffered W: wait for all readers, then overwrite
            __syncthreads();
            const float4* sh = (const float4*)(Whi + (size_t)s * 16384);
            const float4* sl = (const float4*)(Wlo + (size_t)s * 16384);
            #pragma unroll
            for (int u = 0; u < 8; u++) {
                int i = tid + u * 256;
                cp16(W_HI + (uint32_t)i * 16, sh + i);
                cp16(W_LO + (uint32_t)i * 16, sl + i);
            }
            CP_COMMIT();
        }
        CP_WAIT0();
        __syncthreads();

        float acc[2][4][4];
        #pragma unroll
        for (int mt = 0; mt < 2; mt++)
            #pragma unroll
            for (int nt = 0; nt < 4; nt++)
                #pragma unroll
                for (int i = 0; i < 4; i++) acc[mt][nt][i] = 0.f;

        #pragma unroll
        for (int ks = 0; ks < 8; ks++) {
            uint32_t ah[2][4], al[2][4], bh[4][2], bl[4][2];
            #pragma unroll
            for (int mt = 0; mt < 2; mt++) {
                int row = warpM * 32 + mt * 16 + rA;
                int kc  = ks * 2 + kcA;
                uint32_t off = (uint32_t)row * 256 + (uint32_t)((kc ^ (row & 7)) << 4);
                LDSM_X4(ah[mt][0], ah[mt][1], ah[mt][2], ah[mt][3], A_HI + off);
                LDSM_X4(al[mt][0], al[mt][1], al[mt][2], al[mt][3], A_LO + off);
            }
            #pragma unroll
            for (int nt = 0; nt < 4; nt++) {
                int row = warpN * 32 + nt * 8 + rB;
                int kc  = ks * 2 + kcB;
                uint32_t off = (uint32_t)row * 256 + (uint32_t)((kc ^ (row & 7)) << 4);
                LDSM_X2(bh[nt][0], bh[nt][1], W_HI + off);
                LDSM_X2(bl[nt][0], bl[nt][1], W_LO + off);
            }
            #pragma unroll
            for (int mt = 0; mt < 2; mt++)
                #pragma unroll
                for (int nt = 0; nt < 4; nt++) {
                    MMA_BF16(acc[mt][nt], ah[mt][0], ah[mt][1], ah[mt][2], ah[mt][3],
                             bh[nt][0], bh[nt][1]);
                    MMA_BF16(acc[mt][nt], ah[mt][0], ah[mt][1], ah[mt][2], ah[mt][3],
                             bl[nt][0], bl[nt][1]);
                    MMA_BF16(acc[mt][nt], al[mt][0], al[mt][1], al[mt][2], al[mt][3],
                             bh[nt][0], bh[nt][1]);
                }
        }

        // epilogue: bias + store
        #pragma unroll
        for (int mt = 0; mt < 2; mt++) {
            int r0 = rowBase + warpM * 32 + mt * 16 + (lane >> 2);
            int r1 = r0 + 8;
            #pragma unroll
            for (int nt = 0; nt < 4; nt++) {
                int c = warpN * 32 + nt * 8 + ((lane & 3) << 1);
                float bx = __ldg(biasR + s * 128 + c);
                float by = __ldg(biasR + s * 128 + c + 1);
                if (r0 < R) {
                    float2 v = make_float2(acc[mt][nt][0] + bx, acc[mt][nt][1] + by);
                    *(float2*)(out + (size_t)r0 * outStride + s * 128 + c) = v;
                }
                if (r1 < R) {
                    float2 v = make_float2(acc[mt][nt][2] + bx, acc[mt][nt][3] + by);
                    *(float2*)(out + (size_t)r1 * outStride + s * 128 + c) = v;
                }
            }
        }
    }
}

// ---------------- CSR build ------------------------------------------------
__global__ void hist_deg(const int* __restrict__ ei, int* __restrict__ deg, int E)
{
    for (int e = blockIdx.x * blockDim.x + threadIdx.x; e < E;
         e += gridDim.x * blockDim.x)
        atomicAdd(&deg[ei[e]], 1);
}

__global__ void scan1(const int* __restrict__ in, int* __restrict__ out,
                      int* __restrict__ bsum, int n)
{
    __shared__ int s[1024];
    int i = blockIdx.x * 1024 + threadIdx.x;
    int v = (i < n) ? in[i] : 0;
    s[threadIdx.x] = v;
    __syncthreads();
    for (int off = 1; off < 1024; off <<= 1) {
        int t = (threadIdx.x >= off) ? s[threadIdx.x - off] : 0;
        __syncthreads();
        s[threadIdx.x] += t;
        __syncthreads();
    }
    if (i < n) out[i] = s[threadIdx.x] - v;
    if (threadIdx.x == 1023) bsum[blockIdx.x] = s[1023];
}

__global__ void scan2(int* __restrict__ bsum, int nb)
{
    __shared__ int s[1024];
    int v = (threadIdx.x < nb) ? bsum[threadIdx.x] : 0;
    s[threadIdx.x] = v;
    __syncthreads();
    for (int off = 1; off < 1024; off <<= 1) {
        int t = (threadIdx.x >= off) ? s[threadIdx.x - off] : 0;
        __syncthreads();
        s[threadIdx.x] += t;
        __syncthreads();
    }
    if (threadIdx.x < nb) bsum[threadIdx.x] = s[threadIdx.x] - v;
}

__global__ void scan3(int* __restrict__ out, const int* __restrict__ bsum,
                      int n, int total)
{
    int i = blockIdx.x * 1024 + threadIdx.x;
    if (i < n) out[i] += bsum[blockIdx.x];
    if (blockIdx.x == 0 && threadIdx.x == 0) out[n] = total;
}

__global__ void scatter_edges(const int* __restrict__ ei,
                              const int* __restrict__ starts,
                              int* __restrict__ cursor, int* __restrict__ elist, int E)
{
    for (int e = blockIdx.x * blockDim.x + threadIdx.x; e < E;
         e += gridDim.x * blockDim.x) {
        int n = ei[e];
        int p = atomicAdd(&cursor[n], 1);
        elist[starts[n] + p] = e;
    }
}

// ------- edge pass: emsg += P0[i] + P1[j]; accumulate BN stats --------------
// P layout: row stride 512 floats = 128 float4; slot s at float4 offset s*32.
__global__ void __launch_bounds__(256) edge_pass(
    const int* __restrict__ ei, const int* __restrict__ ej,
    const float* __restrict__ P,
    float* __restrict__ emsg, int E, double* __restrict__ stats)
{
    __shared__ float ssum[128], ssq[128];
    if (threadIdx.x < 128) { ssum[threadIdx.x] = 0.f; ssq[threadIdx.x] = 0.f; }
    __syncthreads();
    const int lane = threadIdx.x & 31;
    float4 ls = make_float4(0.f, 0.f, 0.f, 0.f);
    float4 lq = make_float4(0.f, 0.f, 0.f, 0.f);
    const long long total = (long long)E * 32;
    for (long long idx = (long long)blockIdx.x * blockDim.x + threadIdx.x;
         idx < total; idx += (long long)gridDim.x * blockDim.x) {
        int e = (int)(idx >> 5);
        int i = ei[e], j = ej[e];
        float4 v  = ((const float4*)emsg)[idx];
        float4 p0 = ((const float4*)P)[(long long)i * 128 + lane];
        float4 p1 = ((const float4*)P)[(long long)j * 128 + 32 + lane];
        v.x += p0.x + p1.x; v.y += p0.y + p1.y;
        v.z += p0.z + p1.z; v.w += p0.w + p1.w;
        ((float4*)emsg)[idx] = v;
        ls.x += v.x; ls.y += v.y; ls.z += v.z; ls.w += v.w;
        lq.x += v.x * v.x; lq.y += v.y * v.y; lq.z += v.z * v.z; lq.w += v.w * v.w;
    }
    atomicAdd(&ssum[lane * 4 + 0], ls.x); atomicAdd(&ssum[lane * 4 + 1], ls.y);
    atomicAdd(&ssum[lane * 4 + 2], ls.z); atomicAdd(&ssum[lane * 4 + 3], ls.w);
    atomicAdd(&ssq[lane * 4 + 0], lq.x);  atomicAdd(&ssq[lane * 4 + 1], lq.y);
    atomicAdd(&ssq[lane * 4 + 2], lq.z);  atomicAdd(&ssq[lane * 4 + 3], lq.w);
    __syncthreads();
    if (threadIdx.x < 128) {
        atomicAdd(&stats[threadIdx.x],       (double)ssum[threadIdx.x]);
        atomicAdd(&stats[128 + threadIdx.x], (double)ssq[threadIdx.x]);
    }
}

// ------- per-node aggregation (warp per node, CSR gather) -------------------
__global__ void __launch_bounds__(256) node_agg(
    const int* __restrict__ starts, const int* __restrict__ elist,
    const int* __restrict__ ej, const float* __restrict__ emsg,
    const float* __restrict__ P,
    float* __restrict__ h, int nN, double* __restrict__ stats)
{
    __shared__ float ssum[128], ssq[128];
    if (threadIdx.x < 128) { ssum[threadIdx.x] = 0.f; ssq[threadIdx.x] = 0.f; }
    __syncthreads();
    const int lane  = threadIdx.x & 31;
    const int warp  = (blockIdx.x * blockDim.x + threadIdx.x) >> 5;
    const int nwarp = (gridDim.x * blockDim.x) >> 5;
    float4 ls = make_float4(0.f, 0.f, 0.f, 0.f);
    float4 lq = make_float4(0.f, 0.f, 0.f, 0.f);
    for (int n = warp; n < nN; n += nwarp) {
        int s = starts[n], t = starts[n + 1];
        float4 sg = make_float4(0.f, 0.f, 0.f, 0.f);
        float4 sn = make_float4(0.f, 0.f, 0.f, 0.f);
        for (int k = s; k < t; k++) {
            int e = elist[k];
            int j = ej[e];
            float4 v  = ((const float4*)emsg)[(long long)e * 32 + lane];
            float4 sig = make_float4(sigm(v.x), sigm(v.y), sigm(v.z), sigm(v.w));
            float4 p4 = ((const float4*)P)[(long long)j * 128 + 96 + lane];
            sg.x += sig.x; sg.y += sig.y; sg.z += sig.z; sg.w += sig.w;
            sn.x += sig.x * p4.x; sn.y += sig.y * p4.y;
            sn.z += sig.z * p4.z; sn.w += sig.w * p4.w;
        }
        float4 hv = ((const float4*)P)[(long long)n * 128 + 64 + lane];
        hv.x += sn.x / (sg.x + 1e-9f); hv.y += sn.y / (sg.y + 1e-9f);
        hv.z += sn.z / (sg.z + 1e-9f); hv.w += sn.w / (sg.w + 1e-9f);
        ((float4*)h)[(long long)n * 32 + lane] = hv;
        ls.x += hv.x; ls.y += hv.y; ls.z += hv.z; ls.w += hv.w;
        lq.x += hv.x * hv.x; lq.y += hv.y * hv.y;
        lq.z += hv.z * hv.z; lq.w += hv.w * hv.w;
    }
    atomicAdd(&ssum[lane * 4 + 0], ls.x); atomicAdd(&ssum[lane * 4 + 1], ls.y);
    atomicAdd(&ssum[lane * 4 + 2], ls.z); atomicAdd(&ssum[lane * 4 + 3], ls.w);
    atomicAdd(&ssq[lane * 4 + 0], lq.x);  atomicAdd(&ssq[lane * 4 + 1], lq.y);
    atomicAdd(&ssq[lane * 4 + 2], lq.z);  atomicAdd(&ssq[lane * 4 + 3], lq.w);
    __syncthreads();
    if (threadIdx.x < 128) {
        atomicAdd(&stats[threadIdx.x],       (double)ssum[threadIdx.x]);
        atomicAdd(&stats[128 + threadIdx.x], (double)ssq[threadIdx.x]);
    }
}

// ---------------- BN finalize + fused apply ---------------------------------
__global__ void finalize_bn(const double* __restrict__ stats,
                            const float* __restrict__ gamma,
                            const float* __restrict__ beta,
                            double invR, float* __restrict__ scale,
                            float* __restrict__ shift)
{
    int f = threadIdx.x;
    double mu  = stats[f] * invR;
    double var = stats[128 + f] * invR - mu * mu;
    float inv = rsqrtf((float)var + 1e-5f);
    float s = gamma[f] * inv;
    scale[f] = s;
    shift[f] = beta[f] - s * (float)mu;
}

__global__ void apply_bn_silu_res(const float* __restrict__ hbuf,
                                  const float* __restrict__ res,
                                  const float* __restrict__ scale,
                                  const float* __restrict__ shift,
                                  float* __restrict__ out, long long n4)
{
    for (long long idx = (long long)blockIdx.x * blockDim.x + threadIdx.x;
         idx < n4; idx += (long long)gridDim.x * blockDim.x) {
        int l = (int)(idx & 31);
        float4 sc = ((const float4*)scale)[l];
        float4 sh = ((const float4*)shift)[l];
        float4 v = ((const float4*)hbuf)[idx];
        v.x = v.x * sc.x + sh.x; v.y = v.y * sc.y + sh.y;
        v.z = v.z * sc.z + sh.z; v.w = v.w * sc.w + sh.w;
        float4 u = make_float4(v.x * sigm(v.x), v.y * sigm(v.y),
                               v.z * sigm(v.z), v.w * sigm(v.w));
        float4 r = ((const float4*)res)[idx];
        u.x += r.x; u.y += r.y; u.z += r.z; u.w += r.w;
        ((float4*)out)[idx] = u;
    }
}

// ---------------- host orchestration ----------------------------------------
struct Scratch {
    float *P, *emsg, *h;
    int *deg, *starts, *cursor, *elist, *bsum;
    double *statsE, *statsN;
    float *scaleE, *shiftE, *scaleN, *shiftN;
    __nv_bfloat16 *Whi, *Wlo;
    float *biasR;
};

static void run_conv(const Scratch& S, int conv,
                     const int* ei, const int* ej, int nN, int E,
                     const float* xnode, const float* eedge,
                     const float* bng, const float* bnb,
                     const float* node_res, float* node_out,
                     const float* edge_res, float* edge_out)
{
    cudaStream_t st = 0;
    cudaMemsetAsync(S.deg, 0, (size_t)nN * sizeof(int), st);
    cudaMemsetAsync(S.cursor, 0, (size_t)nN * sizeof(int), st);
    cudaMemsetAsync(S.statsE, 0, 256 * sizeof(double), st);
    cudaMemsetAsync(S.statsN, 0, 256 * sizeof(double), st);

    int gbN = (nN + 63) / 64;
    int gbE = (E + 63) / 64;
    const __nv_bfloat16* Whi = S.Whi + (size_t)conv * 5 * 16384;
    const __nv_bfloat16* Wlo = S.Wlo + (size_t)conv * 5 * 16384;
    const float* biasR = S.biasR + conv * 5 * 128;

    // fused node projections (slots 0..3 -> P), edge projection (slot 4 -> emsg)
    gemm_mma<<<gbN, 256, GEMM_SMEM, st>>>(xnode, nN, Whi, Wlo, biasR, 4, S.P, 512);
    gemm_mma<<<gbE, 256, GEMM_SMEM, st>>>(eedge, E, Whi + 4 * 16384, Wlo + 4 * 16384,
                                          biasR + 4 * 128, 1, S.emsg, 128);

    // CSR
    hist_deg<<<2048, 256, 0, st>>>(ei, S.deg, E);
    int nb = (nN + 1023) / 1024;
    scan1<<<nb, 1024, 0, st>>>(S.deg, S.starts, S.bsum, nN);
    scan2<<<1, 1024, 0, st>>>(S.bsum, nb);
    scan3<<<nb, 1024, 0, st>>>(S.starts, S.bsum, nN, E);
    scatter_edges<<<2048, 256, 0, st>>>(ei, S.starts, S.cursor, S.elist, E);

    // edge message + edge-BN stats
    edge_pass<<<4096, 256, 0, st>>>(ei, ej, S.P, S.emsg, E, S.statsE);
    finalize_bn<<<1, 128, 0, st>>>(S.statsE, bng + 0 * 128, bnb + 0 * 128,
                                   1.0 / (double)E, S.scaleE, S.shiftE);

    // node aggregation + node-BN stats
    node_agg<<<4096, 256, 0, st>>>(S.starts, S.elist, ej, S.emsg, S.P,
                                   S.h, nN, S.statsN);
    finalize_bn<<<1, 128, 0, st>>>(S.statsN, bng + 1 * 128, bnb + 1 * 128,
                                   1.0 / (double)nN, S.scaleN, S.shiftN);

    // fused BN + silu + residual
    long long n4n = (long long)nN * 32;
    long long n4e = (long long)E * 32;
    int gbA = (int)((n4n + 255) / 256); if (gbA > 8192) gbA = 8192;
    int gbB = (int)((n4e + 255) / 256); if (gbB > 8192) gbB = 8192;
    apply_bn_silu_res<<<gbA, 256, 0, st>>>(S.h, node_res, S.scaleN, S.shiftN,
                                           node_out, n4n);
    apply_bn_silu_res<<<gbB, 256, 0, st>>>(S.emsg, edge_res, S.scaleE, S.shiftE,
                                           edge_out, n4e);
}

extern "C" void kernel_launch(void* const* d_in, const int* in_sizes, int n_in,
                              void* d_out, int out_size)
{
    const int*   gidx = (const int*)d_in[0];
    const int*   lidx = (const int*)d_in[1];
    const float* x    = (const float*)d_in[2];
    const float* y    = (const float*)d_in[3];
    const float* z    = (const float*)d_in[4];
    const float* W1   = (const float*)d_in[5];
    const float* b1   = (const float*)d_in[6];
    const float* bng1 = (const float*)d_in[7];
    const float* bnb1 = (const float*)d_in[8];
    const float* W2   = (const float*)d_in[9];
    const float* b2   = (const float*)d_in[10];
    const float* bng2 = (const float*)d_in[11];
    const float* bnb2 = (const float*)d_in[12];

    float* xo = (float*)d_out;
    float* yo = xo + (long long)NN1 * F;
    float* zo = yo + (long long)NE1 * F;

    Scratch S;
    cudaGetSymbolAddress((void**)&S.P, g_P);
    cudaGetSymbolAddress((void**)&S.emsg, g_emsg);
    cudaGetSymbolAddress((void**)&S.h, g_h);
    cudaGetSymbolAddress((void**)&S.deg, g_deg);
    cudaGetSymbolAddress((void**)&S.starts, g_starts);
    cudaGetSymbolAddress((void**)&S.cursor, g_cursor);
    cudaGetSymbolAddress((void**)&S.elist, g_elist);
    cudaGetSymbolAddress((void**)&S.bsum, g_bsum);
    cudaGetSymbolAddress((void**)&S.statsE, g_statsE);
    cudaGetSymbolAddress((void**)&S.statsN, g_statsN);
    cudaGetSymbolAddress((void**)&S.scaleE, g_scaleE);
    cudaGetSymbolAddress((void**)&S.shiftE, g_shiftE);
    cudaGetSymbolAddress((void**)&S.scaleN, g_scaleN);
    cudaGetSymbolAddress((void**)&S.shiftN, g_shiftN);
    cudaGetSymbolAddress((void**)&S.Whi, g_Whi);
    cudaGetSymbolAddress((void**)&S.Wlo, g_Wlo);
    cudaGetSymbolAddress((void**)&S.biasR, g_biasR);

    cudaFuncSetAttribute(gemm_mma, cudaFuncAttributeMaxDynamicSharedMemorySize,
                         GEMM_SMEM);

    prep_weights<<<(2 * 5 * 16384 + 255) / 256, 256>>>(W1, b1, W2, b2,
                                                       S.Whi, S.Wlo, S.biasR);

    // conv1: node_update on g
    run_conv(S, 0, gidx, gidx + NE1, NN1, NE1, x, y, bng1, bnb1,
             /*node_res=*/x, /*node_out=*/xo, /*edge_res=*/y, /*edge_out=*/yo);
    // conv2: edge_update on line graph (nodes = m = yo, edges = z)
    run_conv(S, 1, lidx, lidx + NE2, NE1, NE2, yo, z, bng2, bnb2,
             /*node_res=*/yo, /*node_out=*/yo, /*edge_res=*/z, /*edge_out=*/zo);
}

// round 7
// speedup vs baseline: 1.6444x; 1.0528x over previous
#include <cuda_runtime.h>
#include <cuda_bf16.h>
#include <cstdint>

#define F 128
static const int NN1 = 50000;   // nodes in g
static const int NE1 = 400000;  // edges in g == nodes of line graph
static const int NE2 = 800000;  // edges in line graph
#define MAXN 400000
#define MAXE 800000

// ---------------- scratch (device globals: no cudaMalloc allowed) ----------
__device__ float  g_P[(size_t)MAXN * 512];       // [row][slot(4)][128] fused projections
__device__ float  g_emsg[(size_t)MAXE * F];
__device__ float  g_h[(size_t)MAXN * F];
__device__ int    g_deg[MAXN];
__device__ int    g_starts[MAXN + 1];
__device__ int    g_cursor[MAXN];
__device__ int    g_elist[MAXE];
__device__ int    g_bsum[1024];
__device__ double g_statsE[256];
__device__ double g_statsN[256];
__device__ float  g_scaleE[F], g_shiftE[F], g_scaleN[F], g_shiftN[F];
__device__ __nv_bfloat16 g_Whi[2 * 5 * 16384];   // swizzled bf16 weight images
__device__ __nv_bfloat16 g_Wlo[2 * 5 * 16384];
__device__ float  g_biasR[2 * 5 * 128];

__device__ __forceinline__ float sigm(float v) { return 1.0f / (1.0f + __expf(-v)); }

__device__ __forceinline__ uint32_t smem_to_u32(const void* p) {
    uint32_t a;
    asm("{ .reg .u64 t; cvta.to.shared.u64 t, %1; cvt.u32.u64 %0, t; }"
        : "=r"(a) : "l"(p));
    return a;
}
__device__ __forceinline__ void cp16(uint32_t dst, const void* src) {
    asm volatile("cp.async.cg.shared.global [%0], [%1], 16;"
                 :: "r"(dst), "l"(src));
}
#define CP_COMMIT() asm volatile("cp.async.commit_group;")
#define CP_WAIT0()  asm volatile("cp.async.wait_group 0;")

#define LDSM_X4(r0, r1, r2, r3, a) \
    asm volatile("ldmatrix.sync.aligned.m8n8.x4.shared.b16 {%0,%1,%2,%3}, [%4];" \
                 : "=r"(r0), "=r"(r1), "=r"(r2), "=r"(r3) : "r"(a))
#define LDSM_X2(r0, r1, a) \
    asm volatile("ldmatrix.sync.aligned.m8n8.x2.shared.b16 {%0,%1}, [%2];" \
                 : "=r"(r0), "=r"(r1) : "r"(a))
#define MMA_BF16(d, a0, a1, a2, a3, b0, b1) \
    asm volatile("mma.sync.aligned.m16n8k16.row.col.f32.bf16.bf16.f32 " \
                 "{%0,%1,%2,%3},{%4,%5,%6,%7},{%8,%9},{%0,%1,%2,%3};" \
                 : "+f"((d)[0]), "+f"((d)[1]), "+f"((d)[2]), "+f"((d)[3]) \
                 : "r"(a0), "r"(a1), "r"(a2), "r"(a3), "r"(b0), "r"(b1))

// XOR-swizzled bf16 image: row r (256B row), col k; 16B chunks xor'ed by (r&7).
__device__ __host__ __forceinline__ uint32_t sw_byte(int r, int k) {
    return (uint32_t)r * 256u + (uint32_t)(((k >> 3) ^ (r & 7)) << 4)
         + (uint32_t)((k & 7) << 1);
}

// ==================== weight prep: fp32 -> bf16 hi/lo swizzled images =======
__global__ void prep_weights(const float* __restrict__ W1, const float* __restrict__ b1,
                             const float* __restrict__ W2, const float* __restrict__ b2,
                             __nv_bfloat16* __restrict__ Whi,
                             __nv_bfloat16* __restrict__ Wlo,
                             float* __restrict__ biasR)
{
    int idx = blockIdx.x * blockDim.x + threadIdx.x;
    if (idx >= 2 * 5 * 16384) return;
    int c = idx / (5 * 16384);
    int rem = idx % (5 * 16384);
    int s = rem / 16384;
    int e = rem & 16383;
    int n = e >> 7, k = e & 127;
    const int map[5] = {0, 1, 3, 4, 2};   // slots: src_gate,dst_gate,src_upd,dst_upd | edge_gate
    const float* W = (c == 0 ? W1 : W2) + (size_t)map[s] * 16384;
    float a = W[n * 128 + k];
    __nv_bfloat16 h = __float2bfloat16(a);
    __nv_bfloat16 l = __float2bfloat16(a - __bfloat162float(h));
    uint32_t off = sw_byte(n, k) >> 1;
    size_t base = (size_t)(c * 5 + s) * 16384;
    Whi[base + off] = h;
    Wlo[base + off] = l;
    if (e < 128) {
        const float* b = (c == 0 ? b1 : b2);
        biasR[(c * 5 + s) * 128 + e] = b[map[s] * 128 + e];
    }
}

// ==================== HMMA GEMM (256 thr, 8 warps, M=64 tile, 2 CTAs/SM) ====
// node mode: out[r, s*128+c] = A[r] @ W_s^T + b_s   (nW slots)
// edge mode (nW=1): emsg[e] = A[e]@W^T + b + P0[ei[e]] + P1[ej[e]]; BN stats.
// smem: A hi/lo 32KB (reused as fp32 ACC in edge phase 2) + W hi/lo 64KB + 1KB.
static constexpr int GEMM_SMEM = 99328;

__global__ void __launch_bounds__(256, 2) gemm_mma(
    const float* __restrict__ A, int R,
    const __nv_bfloat16* __restrict__ Whi, const __nv_bfloat16* __restrict__ Wlo,
    const float* __restrict__ biasR, int nW,
    float* __restrict__ out, int outStride,
    const int* __restrict__ ei, const int* __restrict__ ej,
    const float* __restrict__ P, double* __restrict__ stats)
{
    extern __shared__ char smem[];
    const uint32_t sb   = smem_to_u32(smem);
    const uint32_t A_HI = sb, A_LO = sb + 16384;
    const uint32_t W_HI = sb + 32768, W_LO = sb + 65536;
    float* ssumS = (float*)(smem + 98304);   // [128]
    float* ssqS  = ssumS + 128;              // [128]
    const int tid = threadIdx.x, lane = tid & 31, wid = tid >> 5;
    const int warpM = wid & 1, warpN = wid >> 1; // warp tile 32m x 32n
    const int rowBase = blockIdx.x * 64;
    const bool EDGE = (ei != nullptr);

    if (EDGE && tid < 128) { ssumS[tid] = 0.f; ssqS[tid] = 0.f; }

    // prefetch W slot 0 (overlaps with A load/convert)
    {
        const float4* sh = (const float4*)Whi;
        const float4* sl = (const float4*)Wlo;
        #pragma unroll
        for (int u = 0; u < 8; u++) {
            int i = tid + u * 256;
            cp16(W_HI + (uint32_t)i * 16, sh + i);
            cp16(W_LO + (uint32_t)i * 16, sl + i);
        }
        CP_COMMIT();
    }

    // load + split A tile (64 rows) into hi/lo swizzled smem
    #pragma unroll
    for (int u = 0; u < 8; u++) {
        int idx = tid + u * 256;          // 0..2047 float4s
        int r = idx >> 5, q = idx & 31;   // row (0..63), k-float4
        float4 a = make_float4(0.f, 0.f, 0.f, 0.f);
        if (rowBase + r < R)
            a = ((const float4*)(A + (size_t)(rowBase + r) * 128))[q];
        __nv_bfloat16 h0 = __float2bfloat16(a.x), h1 = __float2bfloat16(a.y);
        __nv_bfloat16 h2 = __float2bfloat16(a.z), h3 = __float2bfloat16(a.w);
        __nv_bfloat162 hp0 = __nv_bfloat162(h0, h1), hp1 = __nv_bfloat162(h2, h3);
        __nv_bfloat162 lp0 = __nv_bfloat162(
            __float2bfloat16(a.x - __bfloat162float(h0)),
            __float2bfloat16(a.y - __bfloat162float(h1)));
        __nv_bfloat162 lp1 = __nv_bfloat162(
            __float2bfloat16(a.z - __bfloat162float(h2)),
            __float2bfloat16(a.w - __bfloat162float(h3)));
        uint32_t off = (uint32_t)r * 256 + (uint32_t)((((q >> 1)) ^ (r & 7)) << 4)
                     + (uint32_t)((q & 1) << 3);
        uint2 hv, lv;
        hv.x = *(uint32_t*)&hp0; hv.y = *(uint32_t*)&hp1;
        lv.x = *(uint32_t*)&lp0; lv.y = *(uint32_t*)&lp1;
        *(uint2*)(smem + off)         = hv;
        *(uint2*)(smem + 16384 + off) = lv;
    }

    // per-lane ldmatrix address components
    const int gA  = lane >> 3;
    const int rA  = (lane & 7) + ((gA & 1) << 3);
    const int kcA = gA >> 1;
    const int rB  = lane & 7;
    const int kcB = (lane >> 3) & 1;

    for (int s = 0; s < nW; s++) {
        if (s > 0) {
            __syncthreads();
            const float4* sh = (const float4*)(Whi + (size_t)s * 16384);
            const float4* sl = (const float4*)(Wlo + (size_t)s * 16384);
            #pragma unroll
            for (int u = 0; u < 8; u++) {
                int i = tid + u * 256;
                cp16(W_HI + (uint32_t)i * 16, sh + i);
                cp16(W_LO + (uint32_t)i * 16, sl + i);
            }
            CP_COMMIT();
        }
        CP_WAIT0();
        __syncthreads();

        float acc[2][4][4];
        #pragma unroll
        for (int mt = 0; mt < 2; mt++)
            #pragma unroll
            for (int nt = 0; nt < 4; nt++)
                #pragma unroll
                for (int i = 0; i < 4; i++) acc[mt][nt][i] = 0.f;

        #pragma unroll
        for (int ks = 0; ks < 8; ks++) {
            uint32_t ah[2][4], al[2][4], bh[4][2], bl[4][2];
            #pragma unroll
            for (int mt = 0; mt < 2; mt++) {
                int row = warpM * 32 + mt * 16 + rA;
                int kc  = ks * 2 + kcA;
                uint32_t off = (uint32_t)row * 256 + (uint32_t)((kc ^ (row & 7)) << 4);
                LDSM_X4(ah[mt][0], ah[mt][1], ah[mt][2], ah[mt][3], A_HI + off);
                LDSM_X4(al[mt][0], al[mt][1], al[mt][2], al[mt][3], A_LO + off);
            }
            #pragma unroll
            for (int nt = 0; nt < 4; nt++) {
                int row = warpN * 32 + nt * 8 + rB;
                int kc  = ks * 2 + kcB;
                uint32_t off = (uint32_t)row * 256 + (uint32_t)((kc ^ (row & 7)) << 4);
                LDSM_X2(bh[nt][0], bh[nt][1], W_HI + off);
                LDSM_X2(bl[nt][0], bl[nt][1], W_LO + off);
            }
            #pragma unroll
            for (int mt = 0; mt < 2; mt++)
                #pragma unroll
                for (int nt = 0; nt < 4; nt++) {
                    MMA_BF16(acc[mt][nt], ah[mt][0], ah[mt][1], ah[mt][2], ah[mt][3],
                             bh[nt][0], bh[nt][1]);
                    MMA_BF16(acc[mt][nt], ah[mt][0], ah[mt][1], ah[mt][2], ah[mt][3],
                             bl[nt][0], bl[nt][1]);
                    MMA_BF16(acc[mt][nt], al[mt][0], al[mt][1], al[mt][2], al[mt][3],
                             bh[nt][0], bh[nt][1]);
                }
        }

        if (!EDGE) {
            // node-mode epilogue: bias + direct store
            #pragma unroll
            for (int mt = 0; mt < 2; mt++) {
                int r0 = rowBase + warpM * 32 + mt * 16 + (lane >> 2);
                int r1 = r0 + 8;
                #pragma unroll
                for (int nt = 0; nt < 4; nt++) {
                    int c = warpN * 32 + nt * 8 + ((lane & 3) << 1);
                    float bx = __ldg(biasR + s * 128 + c);
                    float by = __ldg(biasR + s * 128 + c + 1);
                    if (r0 < R) {
                        float2 v = make_float2(acc[mt][nt][0] + bx, acc[mt][nt][1] + by);
                        *(float2*)(out + (size_t)r0 * outStride + s * 128 + c) = v;
                    }
                    if (r1 < R) {
                        float2 v = make_float2(acc[mt][nt][2] + bx, acc[mt][nt][3] + by);
                        *(float2*)(out + (size_t)r1 * outStride + s * 128 + c) = v;
                    }
                }
            }
        } else {
            // edge-mode: park acc in smem (A buffers dead), then warp-per-edge
            __syncthreads();   // all warps done reading A_HI/A_LO
            #pragma unroll
            for (int mt = 0; mt < 2; mt++) {
                int rl0 = warpM * 32 + mt * 16 + (lane >> 2);
                #pragma unroll
                for (int nt = 0; nt < 4; nt++) {
                    int c = warpN * 32 + nt * 8 + ((lane & 3) << 1);
                    *(float2*)(smem + (size_t)rl0 * 512 + c * 4) =
                        make_float2(acc[mt][nt][0], acc[mt][nt][1]);
                    *(float2*)(smem + (size_t)(rl0 + 8) * 512 + c * 4) =
                        make_float2(acc[mt][nt][2], acc[mt][nt][3]);
                }
            }
            __syncthreads();

            // phase 2: warp w handles edges rowBase + w*8 .. +7 (coalesced gathers)
            const float4 b4 = ((const float4*)biasR)[lane];
            float4 lsum = make_float4(0.f, 0.f, 0.f, 0.f);
            float4 lsq  = make_float4(0.f, 0.f, 0.f, 0.f);
            int idx_i[8], idx_j[8];
            #pragma unroll
            for (int u = 0; u < 8; u++) {
                int e = rowBase + wid * 8 + u;
                idx_i[u] = __ldg(ei + e);
                idx_j[u] = __ldg(ej + e);
            }
            #pragma unroll
            for (int u = 0; u < 8; u++) {
                int r = wid * 8 + u;
                int e = rowBase + r;
                float4 a  = *(const float4*)(smem + (size_t)r * 512 + lane * 16);
                float4 p0 = __ldg((const float4*)(P + (size_t)idx_i[u] * 512) + lane);
                float4 p1 = __ldg((const float4*)(P + (size_t)idx_j[u] * 512 + 128) + lane);
                float4 v = make_float4(a.x + b4.x + p0.x + p1.x,
                                       a.y + b4.y + p0.y + p1.y,
                                       a.z + b4.z + p0.z + p1.z,
                                       a.w + b4.w + p0.w + p1.w);
                ((float4*)(out + (size_t)e * outStride))[lane] = v;
                lsum.x += v.x; lsum.y += v.y; lsum.z += v.z; lsum.w += v.w;
                lsq.x += v.x * v.x; lsq.y += v.y * v.y;
                lsq.z += v.z * v.z; lsq.w += v.w * v.w;
            }
            atomicAdd(&ssumS[lane * 4 + 0], lsum.x);
            atomicAdd(&ssumS[lane * 4 + 1], lsum.y);
            atomicAdd(&ssumS[lane * 4 + 2], lsum.z);
            atomicAdd(&ssumS[lane * 4 + 3], lsum.w);
            atomicAdd(&ssqS[lane * 4 + 0], lsq.x);
            atomicAdd(&ssqS[lane * 4 + 1], lsq.y);
            atomicAdd(&ssqS[lane * 4 + 2], lsq.z);
            atomicAdd(&ssqS[lane * 4 + 3], lsq.w);
            __syncthreads();
            if (tid < 128) {
                atomicAdd(&stats[tid],       (double)ssumS[tid]);
                atomicAdd(&stats[128 + tid], (double)ssqS[tid]);
            }
        }
    }
}

// ---------------- CSR build ------------------------------------------------
__global__ void hist_deg(const int* __restrict__ ei, int* __restrict__ deg, int E)
{
    for (int e = blockIdx.x * blockDim.x + threadIdx.x; e < E;
         e += gridDim.x * blockDim.x)
        atomicAdd(&deg[ei[e]], 1);
}

__global__ void scan1(const int* __restrict__ in, int* __restrict__ out,
                      int* __restrict__ bsum, int n)
{
    __shared__ int s[1024];
    int i = blockIdx.x * 1024 + threadIdx.x;
    int v = (i < n) ? in[i] : 0;
    s[threadIdx.x] = v;
    __syncthreads();
    for (int off = 1; off < 1024; off <<= 1) {
        int t = (threadIdx.x >= off) ? s[threadIdx.x - off] : 0;
        __syncthreads();
        s[threadIdx.x] += t;
        __syncthreads();
    }
    if (i < n) out[i] = s[threadIdx.x] - v;
    if (threadIdx.x == 1023) bsum[blockIdx.x] = s[1023];
}

__global__ void scan2(int* __restrict__ bsum, int nb)
{
    __shared__ int s[1024];
    int v = (threadIdx.x < nb) ? bsum[threadIdx.x] : 0;
    s[threadIdx.x] = v;
    __syncthreads();
    for (int off = 1; off < 1024; off <<= 1) {
        int t = (threadIdx.x >= off) ? s[threadIdx.x - off] : 0;
        __syncthreads();
        s[threadIdx.x] += t;
        __syncthreads();
    }
    if (threadIdx.x < nb) bsum[threadIdx.x] = s[threadIdx.x] - v;
}

__global__ void scan3(int* __restrict__ out, const int* __restrict__ bsum,
                      int n, int total)
{
    int i = blockIdx.x * 1024 + threadIdx.x;
    if (i < n) out[i] += bsum[blockIdx.x];
    if (blockIdx.x == 0 && threadIdx.x == 0) out[n] = total;
}

__global__ void scatter_edges(const int* __restrict__ ei,
                              const int* __restrict__ starts,
                              int* __restrict__ cursor, int* __restrict__ elist, int E)
{
    for (int e = blockIdx.x * blockDim.x + threadIdx.x; e < E;
         e += gridDim.x * blockDim.x) {
        int n = ei[e];
        int p = atomicAdd(&cursor[n], 1);
        elist[starts[n] + p] = e;
    }
}

// ------- per-node aggregation + fused edge BN/silu/residual -----------------
__global__ void __launch_bounds__(256) node_agg(
    const int* __restrict__ starts, const int* __restrict__ elist,
    const int* __restrict__ ej, const float* __restrict__ emsg,
    const float* __restrict__ P,
    float* __restrict__ h, int nN, double* __restrict__ stats,
    const float* __restrict__ scaleE, const float* __restrict__ shiftE,
    const float* __restrict__ eres, float* __restrict__ eout)
{
    __shared__ float ssum[128], ssq[128];
    if (threadIdx.x < 128) { ssum[threadIdx.x] = 0.f; ssq[threadIdx.x] = 0.f; }
    __syncthreads();
    const int lane  = threadIdx.x & 31;
    const int warp  = (blockIdx.x * blockDim.x + threadIdx.x) >> 5;
    const int nwarp = (gridDim.x * blockDim.x) >> 5;
    const float4 scE = ((const float4*)scaleE)[lane];
    const float4 shE = ((const float4*)shiftE)[lane];
    float4 ls = make_float4(0.f, 0.f, 0.f, 0.f);
    float4 lq = make_float4(0.f, 0.f, 0.f, 0.f);
    for (int n = warp; n < nN; n += nwarp) {
        int s = starts[n], t = starts[n + 1];
        float4 sg = make_float4(0.f, 0.f, 0.f, 0.f);
        float4 sn = make_float4(0.f, 0.f, 0.f, 0.f);
        for (int k = s; k < t; k++) {
            int e = elist[k];
            int j = ej[e];
            float4 v  = ((const float4*)emsg)[(long long)e * 32 + lane];
            float4 sig = make_float4(sigm(v.x), sigm(v.y), sigm(v.z), sigm(v.w));
            float4 p4 = ((const float4*)P)[(long long)j * 128 + 96 + lane];
            sg.x += sig.x; sg.y += sig.y; sg.z += sig.z; sg.w += sig.w;
            sn.x += sig.x * p4.x; sn.y += sig.y * p4.y;
            sn.z += sig.z * p4.z; sn.w += sig.w * p4.w;
            // fused edge update: eout = silu(bn(v)) + eres
            float4 b = make_float4(v.x * scE.x + shE.x, v.y * scE.y + shE.y,
                                   v.z * scE.z + shE.z, v.w * scE.w + shE.w);
            float4 er = ((const float4*)eres)[(long long)e * 32 + lane];
            float4 eo = make_float4(b.x * sigm(b.x) + er.x, b.y * sigm(b.y) + er.y,
                                    b.z * sigm(b.z) + er.z, b.w * sigm(b.w) + er.w);
            ((float4*)eout)[(long long)e * 32 + lane] = eo;
        }
        float4 hv = ((const float4*)P)[(long long)n * 128 + 64 + lane];
        hv.x += sn.x / (sg.x + 1e-9f); hv.y += sn.y / (sg.y + 1e-9f);
        hv.z += sn.z / (sg.z + 1e-9f); hv.w += sn.w / (sg.w + 1e-9f);
        ((float4*)h)[(long long)n * 32 + lane] = hv;
        ls.x += hv.x; ls.y += hv.y; ls.z += hv.z; ls.w += hv.w;
        lq.x += hv.x * hv.x; lq.y += hv.y * hv.y;
        lq.z += hv.z * hv.z; lq.w += hv.w * hv.w;
    }
    atomicAdd(&ssum[lane * 4 + 0], ls.x); atomicAdd(&ssum[lane * 4 + 1], ls.y);
    atomicAdd(&ssum[lane * 4 + 2], ls.z); atomicAdd(&ssum[lane * 4 + 3], ls.w);
    atomicAdd(&ssq[lane * 4 + 0], lq.x);  atomicAdd(&ssq[lane * 4 + 1], lq.y);
    atomicAdd(&ssq[lane * 4 + 2], lq.z);  atomicAdd(&ssq[lane * 4 + 3], lq.w);
    __syncthreads();
    if (threadIdx.x < 128) {
        atomicAdd(&stats[threadIdx.x],       (double)ssum[threadIdx.x]);
        atomicAdd(&stats[128 + threadIdx.x], (double)ssq[threadIdx.x]);
    }
}

// ---------------- BN finalize + fused apply ---------------------------------
__global__ void finalize_bn(const double* __restrict__ stats,
                            const float* __restrict__ gamma,
                            const float* __restrict__ beta,
                            double invR, float* __restrict__ scale,
                            float* __restrict__ shift)
{
    int f = threadIdx.x;
    double mu  = stats[f] * invR;
    double var = stats[128 + f] * invR - mu * mu;
    float inv = rsqrtf((float)var + 1e-5f);
    float s = gamma[f] * inv;
    scale[f] = s;
    shift[f] = beta[f] - s * (float)mu;
}

__global__ void apply_bn_silu_res(const float* __restrict__ hbuf,
                                  const float* __restrict__ res,
                                  const float* __restrict__ scale,
                                  const float* __restrict__ shift,
                                  float* __restrict__ out, long long n4)
{
    for (long long idx = (long long)blockIdx.x * blockDim.x + threadIdx.x;
         idx < n4; idx += (long long)gridDim.x * blockDim.x) {
        int l = (int)(idx & 31);
        float4 sc = ((const float4*)scale)[l];
        float4 sh = ((const float4*)shift)[l];
        float4 v = ((const float4*)hbuf)[idx];
        v.x = v.x * sc.x + sh.x; v.y = v.y * sc.y + sh.y;
        v.z = v.z * sc.z + sh.z; v.w = v.w * sc.w + sh.w;
        float4 u = make_float4(v.x * sigm(v.x), v.y * sigm(v.y),
                               v.z * sigm(v.z), v.w * sigm(v.w));
        float4 r = ((const float4*)res)[idx];
        u.x += r.x; u.y += r.y; u.z += r.z; u.w += r.w;
        ((float4*)out)[idx] = u;
    }
}

// ---------------- host orchestration ----------------------------------------
struct Scratch {
    float *P, *emsg, *h;
    int *deg, *starts, *cursor, *elist, *bsum;
    double *statsE, *statsN;
    float *scaleE, *shiftE, *scaleN, *shiftN;
    __nv_bfloat16 *Whi, *Wlo;
    float *biasR;
};

static void run_conv(const Scratch& S, int conv,
                     const int* ei, const int* ej, int nN, int E,
                     const float* xnode, const float* eedge,
                     const float* bng, const float* bnb,
                     const float* node_res, float* node_out,
                     const float* edge_res, float* edge_out)
{
    cudaStream_t st = 0;
    cudaMemsetAsync(S.deg, 0, (size_t)nN * sizeof(int), st);
    cudaMemsetAsync(S.cursor, 0, (size_t)nN * sizeof(int), st);
    cudaMemsetAsync(S.statsE, 0, 256 * sizeof(double), st);
    cudaMemsetAsync(S.statsN, 0, 256 * sizeof(double), st);

    int gbN = (nN + 63) / 64;
    int gbE = (E + 63) / 64;
    const __nv_bfloat16* Whi = S.Whi + (size_t)conv * 5 * 16384;
    const __nv_bfloat16* Wlo = S.Wlo + (size_t)conv * 5 * 16384;
    const float* biasR = S.biasR + conv * 5 * 128;

    // CSR (independent)
    hist_deg<<<2048, 256, 0, st>>>(ei, S.deg, E);
    int nb = (nN + 1023) / 1024;
    scan1<<<nb, 1024, 0, st>>>(S.deg, S.starts, S.bsum, nN);
    scan2<<<1, 1024, 0, st>>>(S.bsum, nb);
    scan3<<<nb, 1024, 0, st>>>(S.starts, S.bsum, nN, E);
    scatter_edges<<<2048, 256, 0, st>>>(ei, S.starts, S.cursor, S.elist, E);

    // fused node projections (slots 0..3 -> P)
    gemm_mma<<<gbN, 256, GEMM_SMEM, st>>>(xnode, nN, Whi, Wlo, biasR, 4,
                                          S.P, 512, nullptr, nullptr, nullptr,
                                          nullptr);
    // edge projection + phase-2 fused gather-add + BN stats -> emsg
    gemm_mma<<<gbE, 256, GEMM_SMEM, st>>>(eedge, E, Whi + 4 * 16384, Wlo + 4 * 16384,
                                          biasR + 4 * 128, 1, S.emsg, 128,
                                          ei, ej, S.P, S.statsE);
    finalize_bn<<<1, 128, 0, st>>>(S.statsE, bng + 0 * 128, bnb + 0 * 128,
                                   1.0 / (double)E, S.scaleE, S.shiftE);

    // node aggregation + node BN stats + fused edge BN/silu/residual output
    node_agg<<<4096, 256, 0, st>>>(S.starts, S.elist, ej, S.emsg, S.P,
                                   S.h, nN, S.statsN,
                                   S.scaleE, S.shiftE, edge_res, edge_out);
    finalize_bn<<<1, 128, 0, st>>>(S.statsN, bng + 1 * 128, bnb + 1 * 128,
                                   1.0 / (double)nN, S.scaleN, S.shiftN);

    long long n4n = (long long)nN * 32;
    int gbA = (int)((n4n + 255) / 256); if (gbA > 8192) gbA = 8192;
    apply_bn_silu_res<<<gbA, 256, 0, st>>>(S.h, node_res, S.scaleN, S.shiftN,
                                           node_out, n4n);
}

extern "C" void kernel_launch(void* const* d_in, const int* in_sizes, int n_in,
                              void* d_out, int out_size)
{
    const int*   gidx = (const int*)d_in[0];
    const int*   lidx = (const int*)d_in[1];
    const float* x    = (const float*)d_in[2];
    const float* y    = (const float*)d_in[3];
    const float* z    = (const float*)d_in[4];
    const float* W1   = (const float*)d_in[5];
    const float* b1   = (const float*)d_in[6];
    const float* bng1 = (const float*)d_in[7];
    const float* bnb1 = (const float*)d_in[8];
    const float* W2   = (const float*)d_in[9];
    const float* b2   = (const float*)d_in[10];
    const float* bng2 = (const float*)d_in[11];
    const float* bnb2 = (const float*)d_in[12];

    float* xo = (float*)d_out;
    float* yo = xo + (long long)NN1 * F;
    float* zo = yo + (long long)NE1 * F;

    Scratch S;
    cudaGetSymbolAddress((void**)&S.P, g_P);
    cudaGetSymbolAddress((void**)&S.emsg, g_emsg);
    cudaGetSymbolAddress((void**)&S.h, g_h);
    cudaGetSymbolAddress((void**)&S.deg, g_deg);
    cudaGetSymbolAddress((void**)&S.starts, g_starts);
    cudaGetSymbolAddress((void**)&S.cursor, g_cursor);
    cudaGetSymbolAddress((void**)&S.elist, g_elist);
    cudaGetSymbolAddress((void**)&S.bsum, g_bsum);
    cudaGetSymbolAddress((void**)&S.statsE, g_statsE);
    cudaGetSymbolAddress((void**)&S.statsN, g_statsN);
    cudaGetSymbolAddress((void**)&S.scaleE, g_scaleE);
    cudaGetSymbolAddress((void**)&S.shiftE, g_shiftE);
    cudaGetSymbolAddress((void**)&S.scaleN, g_scaleN);
    cudaGetSymbolAddress((void**)&S.shiftN, g_shiftN);
    cudaGetSymbolAddress((void**)&S.Whi, g_Whi);
    cudaGetSymbolAddress((void**)&S.Wlo, g_Wlo);
    cudaGetSymbolAddress((void**)&S.biasR, g_biasR);

    cudaFuncSetAttribute(gemm_mma, cudaFuncAttributeMaxDynamicSharedMemorySize,
                         GEMM_SMEM);

    prep_weights<<<(2 * 5 * 16384 + 255) / 256, 256>>>(W1, b1, W2, b2,
                                                       S.Whi, S.Wlo, S.biasR);

    // conv1: node_update on g
    run_conv(S, 0, gidx, gidx + NE1, NN1, NE1, x, y, bng1, bnb1,
             /*node_res=*/x, /*node_out=*/xo, /*edge_res=*/y, /*edge_out=*/yo);
    // conv2: edge_update on line graph (nodes = m = yo, edges = z)
    run_conv(S, 1, lidx, lidx + NE2, NE1, NE2, yo, z, bng2, bnb2,
             /*node_res=*/yo, /*node_out=*/yo, /*edge_res=*/z, /*edge_out=*/zo);
}

// round 9
// speedup vs baseline: 1.7127x; 1.0416x over previous
#include <cuda_runtime.h>
#include <cuda_bf16.h>
#include <cuda_fp16.h>
#include <cstdint>

#define F 128
static const int NN1 = 50000;   // nodes in g
static const int NE1 = 400000;  // edges in g == nodes of line graph
static const int NE2 = 800000;  // edges in line graph
#define MAXN 400000
#define MAXE 800000

// ---------------- scratch (device globals: no cudaMalloc allowed) ----------
__device__ __half  g_P[(size_t)MAXN * 512];      // [row][slot(4)][128] fp16 projections
__device__ __half  g_emsg[(size_t)MAXE * F];     // fp16 edge messages
__device__ float   g_h[(size_t)MAXN * F];
__device__ int     g_deg[MAXN];
__device__ int     g_starts[MAXN + 1];
__device__ int     g_cursor[MAXN];
__device__ int     g_elist[MAXE];
__device__ int     g_bsum[1024];
__device__ double  g_statsE[256];
__device__ double  g_statsN[256];
__device__ float   g_scaleE[F], g_shiftE[F], g_scaleN[F], g_shiftN[F];
__device__ __nv_bfloat16 g_Whi[2 * 5 * 16384];   // swizzled bf16 weight images
__device__ __nv_bfloat16 g_Wlo[2 * 5 * 16384];
__device__ float   g_biasR[2 * 5 * 128];

__device__ __forceinline__ float sigm(float v) { return 1.0f / (1.0f + __expf(-v)); }

__device__ __forceinline__ float4 h4_to_f4(uint2 u) {
    __half2 a = *(__half2*)&u.x, b = *(__half2*)&u.y;
    float2 fa = __half22float2(a), fb = __half22float2(b);
    return make_float4(fa.x, fa.y, fb.x, fb.y);
}
__device__ __forceinline__ uint2 f4_to_h4(float4 v) {
    __half2 a = __float22half2_rn(make_float2(v.x, v.y));
    __half2 b = __float22half2_rn(make_float2(v.z, v.w));
    uint2 u; u.x = *(uint32_t*)&a; u.y = *(uint32_t*)&b; return u;
}

__device__ __forceinline__ uint32_t smem_to_u32(const void* p) {
    uint32_t a;
    asm("{ .reg .u64 t; cvta.to.shared.u64 t, %1; cvt.u32.u64 %0, t; }"
        : "=r"(a) : "l"(p));
    return a;
}
__device__ __forceinline__ void cp16(uint32_t dst, const void* src) {
    asm volatile("cp.async.cg.shared.global [%0], [%1], 16;"
                 :: "r"(dst), "l"(src));
}
#define CP_COMMIT() asm volatile("cp.async.commit_group;")
#define CP_WAIT0()  asm volatile("cp.async.wait_group 0;")

#define LDSM_X4(r0, r1, r2, r3, a) \
    asm volatile("ldmatrix.sync.aligned.m8n8.x4.shared.b16 {%0,%1,%2,%3}, [%4];" \
                 : "=r"(r0), "=r"(r1), "=r"(r2), "=r"(r3) : "r"(a))
#define LDSM_X2(r0, r1, a) \
    asm volatile("ldmatrix.sync.aligned.m8n8.x2.shared.b16 {%0,%1}, [%2];" \
                 : "=r"(r0), "=r"(r1) : "r"(a))
#define MMA_BF16(d, a0, a1, a2, a3, b0, b1) \
    asm volatile("mma.sync.aligned.m16n8k16.row.col.f32.bf16.bf16.f32 " \
                 "{%0,%1,%2,%3},{%4,%5,%6,%7},{%8,%9},{%0,%1,%2,%3};" \
                 : "+f"((d)[0]), "+f"((d)[1]), "+f"((d)[2]), "+f"((d)[3]) \
                 : "r"(a0), "r"(a1), "r"(a2), "r"(a3), "r"(b0), "r"(b1))

// XOR-swizzled bf16 image: row r (256B row), col k; 16B chunks xor'ed by (r&7).
__device__ __host__ __forceinline__ uint32_t sw_byte(int r, int k) {
    return (uint32_t)r * 256u + (uint32_t)(((k >> 3) ^ (r & 7)) << 4)
         + (uint32_t)((k & 7) << 1);
}

// ==================== weight prep: fp32 -> bf16 hi/lo swizzled images =======
__global__ void prep_weights(const float* __restrict__ W1, const float* __restrict__ b1,
                             const float* __restrict__ W2, const float* __restrict__ b2,
                             __nv_bfloat16* __restrict__ Whi,
                             __nv_bfloat16* __restrict__ Wlo,
                             float* __restrict__ biasR)
{
    int idx = blockIdx.x * blockDim.x + threadIdx.x;
    if (idx >= 2 * 5 * 16384) return;
    int c = idx / (5 * 16384);
    int rem = idx % (5 * 16384);
    int s = rem / 16384;
    int e = rem & 16383;
    int n = e >> 7, k = e & 127;
    const int map[5] = {0, 1, 3, 4, 2};   // slots: src_gate,dst_gate,src_upd,dst_upd | edge_gate
    const float* W = (c == 0 ? W1 : W2) + (size_t)map[s] * 16384;
    float a = W[n * 128 + k];
    __nv_bfloat16 h = __float2bfloat16(a);
    __nv_bfloat16 l = __float2bfloat16(a - __bfloat162float(h));
    uint32_t off = sw_byte(n, k) >> 1;
    size_t base = (size_t)(c * 5 + s) * 16384;
    Whi[base + off] = h;
    Wlo[base + off] = l;
    if (e < 128) {
        const float* b = (c == 0 ? b1 : b2);
        biasR[(c * 5 + s) * 128 + e] = b[map[s] * 128 + e];
    }
}

// ==================== HMMA GEMM (256 thr, 8 warps, M=64 tile, 2 CTAs/SM) ====
// node mode: out[r, s*128+c] = half(A[r] @ W_s^T + b_s)   (nW slots)
// edge mode (nW=1): emsg[e] = half(A[e]@W^T + b + P0[ei] + P1[ej]); BN stats.
static constexpr int GEMM_SMEM = 99328;

__global__ void __launch_bounds__(256, 2) gemm_mma(
    const float* __restrict__ A, int R,
    const __nv_bfloat16* __restrict__ Whi, const __nv_bfloat16* __restrict__ Wlo,
    const float* __restrict__ biasR, int nW,
    __half* __restrict__ out, int outStride,
    const int* __restrict__ ei, const int* __restrict__ ej,
    const __half* __restrict__ P, double* __restrict__ stats)
{
    extern __shared__ char smem[];
    const uint32_t sb   = smem_to_u32(smem);
    const uint32_t A_HI = sb, A_LO = sb + 16384;
    const uint32_t W_HI = sb + 32768, W_LO = sb + 65536;
    float* ssumS = (float*)(smem + 98304);   // [128]
    float* ssqS  = ssumS + 128;              // [128]
    const int tid = threadIdx.x, lane = tid & 31, wid = tid >> 5;
    const int warpM = wid & 1, warpN = wid >> 1; // warp tile 32m x 32n
    const int rowBase = blockIdx.x * 64;
    const bool EDGE = (ei != nullptr);

    if (EDGE && tid < 128) { ssumS[tid] = 0.f; ssqS[tid] = 0.f; }

    // prefetch W slot 0 (overlaps with A load/convert)
    {
        const float4* sh = (const float4*)Whi;
        const float4* sl = (const float4*)Wlo;
        #pragma unroll
        for (int u = 0; u < 8; u++) {
            int i = tid + u * 256;
            cp16(W_HI + (uint32_t)i * 16, sh + i);
            cp16(W_LO + (uint32_t)i * 16, sl + i);
        }
        CP_COMMIT();
    }

    // load + split A tile (64 rows) into hi/lo swizzled smem
    #pragma unroll
    for (int u = 0; u < 8; u++) {
        int idx = tid + u * 256;          // 0..2047 float4s
        int r = idx >> 5, q = idx & 31;   // row (0..63), k-float4
        float4 a = make_float4(0.f, 0.f, 0.f, 0.f);
        if (rowBase + r < R)
            a = ((const float4*)(A + (size_t)(rowBase + r) * 128))[q];
        __nv_bfloat16 h0 = __float2bfloat16(a.x), h1 = __float2bfloat16(a.y);
        __nv_bfloat16 h2 = __float2bfloat16(a.z), h3 = __float2bfloat16(a.w);
        __nv_bfloat162 hp0 = __nv_bfloat162(h0, h1), hp1 = __nv_bfloat162(h2, h3);
        __nv_bfloat162 lp0 = __nv_bfloat162(
            __float2bfloat16(a.x - __bfloat162float(h0)),
            __float2bfloat16(a.y - __bfloat162float(h1)));
        __nv_bfloat162 lp1 = __nv_bfloat162(
            __float2bfloat16(a.z - __bfloat162float(h2)),
            __float2bfloat16(a.w - __bfloat162float(h3)));
        uint32_t off = (uint32_t)r * 256 + (uint32_t)((((q >> 1)) ^ (r & 7)) << 4)
                     + (uint32_t)((q & 1) << 3);
        uint2 hv, lv;
        hv.x = *(uint32_t*)&hp0; hv.y = *(uint32_t*)&hp1;
        lv.x = *(uint32_t*)&lp0; lv.y = *(uint32_t*)&lp1;
        *(uint2*)(smem + off)         = hv;
        *(uint2*)(smem + 16384 + off) = lv;
    }

    // per-lane ldmatrix address components
    const int gA  = lane >> 3;
    const int rA  = (lane & 7) + ((gA & 1) << 3);
    const int kcA = gA >> 1;
    const int rB  = lane & 7;
    const int kcB = (lane >> 3) & 1;

    for (int s = 0; s < nW; s++) {
        if (s > 0) {
            __syncthreads();
            const float4* sh = (const float4*)(Whi + (size_t)s * 16384);
            const float4* sl = (const float4*)(Wlo + (size_t)s * 16384);
            #pragma unroll
            for (int u = 0; u < 8; u++) {
                int i = tid + u * 256;
                cp16(W_HI + (uint32_t)i * 16, sh + i);
                cp16(W_LO + (uint32_t)i * 16, sl + i);
            }
            CP_COMMIT();
        }
        CP_WAIT0();
        __syncthreads();

        float acc[2][4][4];
        #pragma unroll
        for (int mt = 0; mt < 2; mt++)
            #pragma unroll
            for (int nt = 0; nt < 4; nt++)
                #pragma unroll
                for (int i = 0; i < 4; i++) acc[mt][nt][i] = 0.f;

        #pragma unroll
        for (int ks = 0; ks < 8; ks++) {
            uint32_t ah[2][4], al[2][4], bh[4][2], bl[4][2];
            #pragma unroll
            for (int mt = 0; mt < 2; mt++) {
                int row = warpM * 32 + mt * 16 + rA;
                int kc  = ks * 2 + kcA;
                uint32_t off = (uint32_t)row * 256 + (uint32_t)((kc ^ (row & 7)) << 4);
                LDSM_X4(ah[mt][0], ah[mt][1], ah[mt][2], ah[mt][3], A_HI + off);
                LDSM_X4(al[mt][0], al[mt][1], al[mt][2], al[mt][3], A_LO + off);
            }
            #pragma unroll
            for (int nt = 0; nt < 4; nt++) {
                int row = warpN * 32 + nt * 8 + rB;
                int kc  = ks * 2 + kcB;
                uint32_t off = (uint32_t)row * 256 + (uint32_t)((kc ^ (row & 7)) << 4);
                LDSM_X2(bh[nt][0], bh[nt][1], W_HI + off);
                LDSM_X2(bl[nt][0], bl[nt][1], W_LO + off);
            }
            #pragma unroll
            for (int mt = 0; mt < 2; mt++)
                #pragma unroll
                for (int nt = 0; nt < 4; nt++) {
                    MMA_BF16(acc[mt][nt], ah[mt][0], ah[mt][1], ah[mt][2], ah[mt][3],
                             bh[nt][0], bh[nt][1]);
                    MMA_BF16(acc[mt][nt], ah[mt][0], ah[mt][1], ah[mt][2], ah[mt][3],
                             bl[nt][0], bl[nt][1]);
                    MMA_BF16(acc[mt][nt], al[mt][0], al[mt][1], al[mt][2], al[mt][3],
                             bh[nt][0], bh[nt][1]);
                }
        }

        if (!EDGE) {
            // node-mode epilogue: bias + fp16 store
            #pragma unroll
            for (int mt = 0; mt < 2; mt++) {
                int r0 = rowBase + warpM * 32 + mt * 16 + (lane >> 2);
                int r1 = r0 + 8;
                #pragma unroll
                for (int nt = 0; nt < 4; nt++) {
                    int c = warpN * 32 + nt * 8 + ((lane & 3) << 1);
                    float bx = __ldg(biasR + s * 128 + c);
                    float by = __ldg(biasR + s * 128 + c + 1);
                    if (r0 < R) {
                        __half2 v = __float22half2_rn(
                            make_float2(acc[mt][nt][0] + bx, acc[mt][nt][1] + by));
                        *(__half2*)(out + (size_t)r0 * outStride + s * 128 + c) = v;
                    }
                    if (r1 < R) {
                        __half2 v = __float22half2_rn(
                            make_float2(acc[mt][nt][2] + bx, acc[mt][nt][3] + by));
                        *(__half2*)(out + (size_t)r1 * outStride + s * 128 + c) = v;
                    }
                }
            }
        } else {
            // edge-mode: park acc in smem (A buffers dead), then warp-per-edge
            __syncthreads();   // all warps done reading A_HI/A_LO
            #pragma unroll
            for (int mt = 0; mt < 2; mt++) {
                int rl0 = warpM * 32 + mt * 16 + (lane >> 2);
                #pragma unroll
                for (int nt = 0; nt < 4; nt++) {
                    int c = warpN * 32 + nt * 8 + ((lane & 3) << 1);
                    *(float2*)(smem + (size_t)rl0 * 512 + c * 4) =
                        make_float2(acc[mt][nt][0], acc[mt][nt][1]);
                    *(float2*)(smem + (size_t)(rl0 + 8) * 512 + c * 4) =
                        make_float2(acc[mt][nt][2], acc[mt][nt][3]);
                }
            }
            __syncthreads();

            // phase 2: warp w handles edges rowBase + w*8 .. +7 (coalesced)
            const float4 b4 = ((const float4*)biasR)[lane];
            float4 lsum = make_float4(0.f, 0.f, 0.f, 0.f);
            float4 lsq  = make_float4(0.f, 0.f, 0.f, 0.f);
            int idx_i[8], idx_j[8];
            #pragma unroll
            for (int u = 0; u < 8; u++) {
                int e = rowBase + wid * 8 + u;
                idx_i[u] = __ldg(ei + e);
                idx_j[u] = __ldg(ej + e);
            }
            const uint2* Pu = (const uint2*)P;   // row stride 128 uint2
            #pragma unroll
            for (int u = 0; u < 8; u++) {
                int r = wid * 8 + u;
                int e = rowBase + r;
                float4 a  = *(const float4*)(smem + (size_t)r * 512 + lane * 16);
                float4 p0 = h4_to_f4(__ldg(Pu + (size_t)idx_i[u] * 128 + lane));
                float4 p1 = h4_to_f4(__ldg(Pu + (size_t)idx_j[u] * 128 + 32 + lane));
                float4 v = make_float4(a.x + b4.x + p0.x + p1.x,
                                       a.y + b4.y + p0.y + p1.y,
                                       a.z + b4.z + p0.z + p1.z,
                                       a.w + b4.w + p0.w + p1.w);
                ((uint2*)(out + (size_t)e * outStride))[lane] = f4_to_h4(v);
                lsum.x += v.x; lsum.y += v.y; lsum.z += v.z; lsum.w += v.w;
                lsq.x += v.x * v.x; lsq.y += v.y * v.y;
                lsq.z += v.z * v.z; lsq.w += v.w * v.w;
            }
            atomicAdd(&ssumS[lane * 4 + 0], lsum.x);
            atomicAdd(&ssumS[lane * 4 + 1], lsum.y);
            atomicAdd(&ssumS[lane * 4 + 2], lsum.z);
            atomicAdd(&ssumS[lane * 4 + 3], lsum.w);
            atomicAdd(&ssqS[lane * 4 + 0], lsq.x);
            atomicAdd(&ssqS[lane * 4 + 1], lsq.y);
            atomicAdd(&ssqS[lane * 4 + 2], lsq.z);
            atomicAdd(&ssqS[lane * 4 + 3], lsq.w);
            __syncthreads();
            if (tid < 128) {
                atomicAdd(&stats[tid],       (double)ssumS[tid]);
                atomicAdd(&stats[128 + tid], (double)ssqS[tid]);
            }
        }
    }
}

// ---------------- CSR build ------------------------------------------------
__global__ void hist_deg(const int* __restrict__ ei, int* __restrict__ deg, int E)
{
    for (int e = blockIdx.x * blockDim.x + threadIdx.x; e < E;
         e += gridDim.x * blockDim.x)
        atomicAdd(&deg[ei[e]], 1);
}

__global__ void scan1(const int* __restrict__ in, int* __restrict__ out,
                      int* __restrict__ bsum, int n)
{
    __shared__ int s[1024];
    int i = blockIdx.x * 1024 + threadIdx.x;
    int v = (i < n) ? in[i] : 0;
    s[threadIdx.x] = v;
    __syncthreads();
    for (int off = 1; off < 1024; off <<= 1) {
        int t = (threadIdx.x >= off) ? s[threadIdx.x - off] : 0;
        __syncthreads();
        s[threadIdx.x] += t;
        __syncthreads();
    }
    if (i < n) out[i] = s[threadIdx.x] - v;
    if (threadIdx.x == 1023) bsum[blockIdx.x] = s[1023];
}

__global__ void scan2(int* __restrict__ bsum, int nb)
{
    __shared__ int s[1024];
    int v = (threadIdx.x < nb) ? bsum[threadIdx.x] : 0;
    s[threadIdx.x] = v;
    __syncthreads();
    for (int off = 1; off < 1024; off <<= 1) {
        int t = (threadIdx.x >= off) ? s[threadIdx.x - off] : 0;
        __syncthreads();
        s[threadIdx.x] += t;
        __syncthreads();
    }
    if (threadIdx.x < nb) bsum[threadIdx.x] = s[threadIdx.x] - v;
}

__global__ void scan3(int* __restrict__ out, const int* __restrict__ bsum,
                      int n, int total)
{
    int i = blockIdx.x * 1024 + threadIdx.x;
    if (i < n) out[i] += bsum[blockIdx.x];
    if (blockIdx.x == 0 && threadIdx.x == 0) out[n] = total;
}

__global__ void scatter_edges(const int* __restrict__ ei,
                              const int* __restrict__ starts,
                              int* __restrict__ cursor, int* __restrict__ elist, int E)
{
    for (int e = blockIdx.x * blockDim.x + threadIdx.x; e < E;
         e += gridDim.x * blockDim.x) {
        int n = ei[e];
        int p = atomicAdd(&cursor[n], 1);
        elist[starts[n] + p] = e;
    }
}

// ------- per-node aggregation + fused edge BN/silu/residual -----------------
__global__ void __launch_bounds__(256) node_agg(
    const int* __restrict__ starts, const int* __restrict__ elist,
    const int* __restrict__ ej, const __half* __restrict__ emsg,
    const __half* __restrict__ P,
    float* __restrict__ h, int nN, double* __restrict__ stats,
    const float* __restrict__ scaleE, const float* __restrict__ shiftE,
    const float* __restrict__ eres, float* __restrict__ eout)
{
    __shared__ float ssum[128], ssq[128];
    if (threadIdx.x < 128) { ssum[threadIdx.x] = 0.f; ssq[threadIdx.x] = 0.f; }
    __syncthreads();
    const int lane  = threadIdx.x & 31;
    const int warp  = (blockIdx.x * blockDim.x + threadIdx.x) >> 5;
    const int nwarp = (gridDim.x * blockDim.x) >> 5;
    const float4 scE = ((const float4*)scaleE)[lane];
    const float4 shE = ((const float4*)shiftE)[lane];
    const uint2* Eu = (const uint2*)emsg;   // row stride 32 uint2
    const uint2* Pu = (const uint2*)P;      // row stride 128 uint2
    float4 ls = make_float4(0.f, 0.f, 0.f, 0.f);
    float4 lq = make_float4(0.f, 0.f, 0.f, 0.f);
    for (int n = warp; n < nN; n += nwarp) {
        int s = starts[n], t = starts[n + 1];
        float4 sg = make_float4(0.f, 0.f, 0.f, 0.f);
        float4 sn = make_float4(0.f, 0.f, 0.f, 0.f);
        for (int k = s; k < t; k++) {
            int e = elist[k];
            int j = ej[e];
            float4 v  = h4_to_f4(__ldg(Eu + (size_t)e * 32 + lane));
            float4 sig = make_float4(sigm(v.x), sigm(v.y), sigm(v.z), sigm(v.w));
            float4 p4 = h4_to_f4(__ldg(Pu + (size_t)j * 128 + 96 + lane));
            sg.x += sig.x; sg.y += sig.y; sg.z += sig.z; sg.w += sig.w;
            sn.x += sig.x * p4.x; sn.y += sig.y * p4.y;
            sn.z += sig.z * p4.z; sn.w += sig.w * p4.w;
            // fused edge update: eout = silu(bn(v)) + eres
            float4 b = make_float4(v.x * scE.x + shE.x, v.y * scE.y + shE.y,
                                   v.z * scE.z + shE.z, v.w * scE.w + shE.w);
            float4 er = ((const float4*)eres)[(long long)e * 32 + lane];
            float4 eo = make_float4(b.x * sigm(b.x) + er.x, b.y * sigm(b.y) + er.y,
                                    b.z * sigm(b.z) + er.z, b.w * sigm(b.w) + er.w);
            ((float4*)eout)[(long long)e * 32 + lane] = eo;
        }
        float4 hv = h4_to_f4(__ldg(Pu + (size_t)n * 128 + 64 + lane));
        hv.x += sn.x / (sg.x + 1e-9f); hv.y += sn.y / (sg.y + 1e-9f);
        hv.z += sn.z / (sg.z + 1e-9f); hv.w += sn.w / (sg.w + 1e-9f);
        ((float4*)h)[(long long)n * 32 + lane] = hv;
        ls.x += hv.x; ls.y += hv.y; ls.z += hv.z; ls.w += hv.w;
        lq.x += hv.x * hv.x; lq.y += hv.y * hv.y;
        lq.z += hv.z * hv.z; lq.w += hv.w * hv.w;
    }
    atomicAdd(&ssum[lane * 4 + 0], ls.x); atomicAdd(&ssum[lane * 4 + 1], ls.y);
    atomicAdd(&ssum[lane * 4 + 2], ls.z); atomicAdd(&ssum[lane * 4 + 3], ls.w);
    atomicAdd(&ssq[lane * 4 + 0], lq.x);  atomicAdd(&ssq[lane * 4 + 1], lq.y);
    atomicAdd(&ssq[lane * 4 + 2], lq.z);  atomicAdd(&ssq[lane * 4 + 3], lq.w);
    __syncthreads();
    if (threadIdx.x < 128) {
        atomicAdd(&stats[threadIdx.x],       (double)ssum[threadIdx.x]);
        atomicAdd(&stats[128 + threadIdx.x], (double)ssq[threadIdx.x]);
    }
}

// ---------------- BN finalize + fused apply ---------------------------------
__global__ void finalize_bn(const double* __restrict__ stats,
                            const float* __restrict__ gamma,
                            const float* __restrict__ beta,
                            double invR, float* __restrict__ scale,
                            float* __restrict__ shift)
{
    int f = threadIdx.x;
    double mu  = stats[f] * invR;
    double var = stats[128 + f] * invR - mu * mu;
    float inv = rsqrtf((float)var + 1e-5f);
    float s = gamma[f] * inv;
    scale[f] = s;
    shift[f] = beta[f] - s * (float)mu;
}

__global__ void apply_bn_silu_res(const float* __restrict__ hbuf,
                                  const float* __restrict__ res,
                                  const float* __restrict__ scale,
                                  const float* __restrict__ shift,
                                  float* __restrict__ out, long long n4)
{
    for (long long idx = (long long)blockIdx.x * blockDim.x + threadIdx.x;
         idx < n4; idx += (long long)gridDim.x * blockDim.x) {
        int l = (int)(idx & 31);
        float4 sc = ((const float4*)scale)[l];
        float4 sh = ((const float4*)shift)[l];
        float4 v = ((const float4*)hbuf)[idx];
        v.x = v.x * sc.x + sh.x; v.y = v.y * sc.y + sh.y;
        v.z = v.z * sc.z + sh.z; v.w = v.w * sc.w + sh.w;
        float4 u = make_float4(v.x * sigm(v.x), v.y * sigm(v.y),
                               v.z * sigm(v.z), v.w * sigm(v.w));
        float4 r = ((const float4*)res)[idx];
        u.x += r.x; u.y += r.y; u.z += r.z; u.w += r.w;
        ((float4*)out)[idx] = u;
    }
}

// ---------------- host orchestration ----------------------------------------
struct Scratch {
    __half *P, *emsg;
    float *h;
    int *deg, *starts, *cursor, *elist, *bsum;
    double *statsE, *statsN;
    float *scaleE, *shiftE, *scaleN, *shiftN;
    __nv_bfloat16 *Whi, *Wlo;
    float *biasR;
};

static void run_conv(const Scratch& S, int conv,
                     const int* ei, const int* ej, int nN, int E,
                     const float* xnode, const float* eedge,
                     const float* bng, const float* bnb,
                     const float* node_res, float* node_out,
                     const float* edge_res, float* edge_out)
{
    cudaStream_t st = 0;
    cudaMemsetAsync(S.deg, 0, (size_t)nN * sizeof(int), st);
    cudaMemsetAsync(S.cursor, 0, (size_t)nN * sizeof(int), st);
    cudaMemsetAsync(S.statsE, 0, 256 * sizeof(double), st);
    cudaMemsetAsync(S.statsN, 0, 256 * sizeof(double), st);

    int gbN = (nN + 63) / 64;
    int gbE = (E + 63) / 64;
    const __nv_bfloat16* Whi = S.Whi + (size_t)conv * 5 * 16384;
    const __nv_bfloat16* Wlo = S.Wlo + (size_t)conv * 5 * 16384;
    const float* biasR = S.biasR + conv * 5 * 128;

    // CSR (independent)
    hist_deg<<<2048, 256, 0, st>>>(ei, S.deg, E);
    int nb = (nN + 1023) / 1024;
    scan1<<<nb, 1024, 0, st>>>(S.deg, S.starts, S.bsum, nN);
    scan2<<<1, 1024, 0, st>>>(S.bsum, nb);
    scan3<<<nb, 1024, 0, st>>>(S.starts, S.bsum, nN, E);
    scatter_edges<<<2048, 256, 0, st>>>(ei, S.starts, S.cursor, S.elist, E);

    // fused node projections (slots 0..3 -> P, fp16)
    gemm_mma<<<gbN, 256, GEMM_SMEM, st>>>(xnode, nN, Whi, Wlo, biasR, 4,
                                          S.P, 512, nullptr, nullptr, nullptr,
                                          nullptr);
    // edge projection + phase-2 fused gather-add + BN stats -> emsg (fp16)
    gemm_mma<<<gbE, 256, GEMM_SMEM, st>>>(eedge, E, Whi + 4 * 16384, Wlo + 4 * 16384,
                                          biasR + 4 * 128, 1, S.emsg, 128,
                                          ei, ej, S.P, S.statsE);
    finalize_bn<<<1, 128, 0, st>>>(S.statsE, bng + 0 * 128, bnb + 0 * 128,
                                   1.0 / (double)E, S.scaleE, S.shiftE);

    // node aggregation + node BN stats + fused edge BN/silu/residual output
    node_agg<<<4096, 256, 0, st>>>(S.starts, S.elist, ej, S.emsg, S.P,
                                   S.h, nN, S.statsN,
                                   S.scaleE, S.shiftE, edge_res, edge_out);
    finalize_bn<<<1, 128, 0, st>>>(S.statsN, bng + 1 * 128, bnb + 1 * 128,
                                   1.0 / (double)nN, S.scaleN, S.shiftN);

    long long n4n = (long long)nN * 32;
    int gbA = (int)((n4n + 255) / 256); if (gbA > 8192) gbA = 8192;
    apply_bn_silu_res<<<gbA, 256, 0, st>>>(S.h, node_res, S.scaleN, S.shiftN,
                                           node_out, n4n);
}

extern "C" void kernel_launch(void* const* d_in, const int* in_sizes, int n_in,
                              void* d_out, int out_size)
{
    const int*   gidx = (const int*)d_in[0];
    const int*   lidx = (const int*)d_in[1];
    const float* x    = (const float*)d_in[2];
    const float* y    = (const float*)d_in[3];
    const float* z    = (const float*)d_in[4];
    const float* W1   = (const float*)d_in[5];
    const float* b1   = (const float*)d_in[6];
    const float* bng1 = (const float*)d_in[7];
    const float* bnb1 = (const float*)d_in[8];
    const float* W2   = (const float*)d_in[9];
    const float* b2   = (const float*)d_in[10];
    const float* bng2 = (const float*)d_in[11];
    const float* bnb2 = (const float*)d_in[12];

    float* xo = (float*)d_out;
    float* yo = xo + (long long)NN1 * F;
    float* zo = yo + (long long)NE1 * F;

    Scratch S;
    cudaGetSymbolAddress((void**)&S.P, g_P);
    cudaGetSymbolAddress((void**)&S.emsg, g_emsg);
    cudaGetSymbolAddress((void**)&S.h, g_h);
    cudaGetSymbolAddress((void**)&S.deg, g_deg);
    cudaGetSymbolAddress((void**)&S.starts, g_starts);
    cudaGetSymbolAddress((void**)&S.cursor, g_cursor);
    cudaGetSymbolAddress((void**)&S.elist, g_elist);
    cudaGetSymbolAddress((void**)&S.bsum, g_bsum);
    cudaGetSymbolAddress((void**)&S.statsE, g_statsE);
    cudaGetSymbolAddress((void**)&S.statsN, g_statsN);
    cudaGetSymbolAddress((void**)&S.scaleE, g_scaleE);
    cudaGetSymbolAddress((void**)&S.shiftE, g_shiftE);
    cudaGetSymbolAddress((void**)&S.scaleN, g_scaleN);
    cudaGetSymbolAddress((void**)&S.shiftN, g_shiftN);
    cudaGetSymbolAddress((void**)&S.Whi, g_Whi);
    cudaGetSymbolAddress((void**)&S.Wlo, g_Wlo);
    cudaGetSymbolAddress((void**)&S.biasR, g_biasR);

    cudaFuncSetAttribute(gemm_mma, cudaFuncAttributeMaxDynamicSharedMemorySize,
                         GEMM_SMEM);

    prep_weights<<<(2 * 5 * 16384 + 255) / 256, 256>>>(W1, b1, W2, b2,
                                                       S.Whi, S.Wlo, S.biasR);

    // conv1: node_update on g
    run_conv(S, 0, gidx, gidx + NE1, NN1, NE1, x, y, bng1, bnb1,
             /*node_res=*/x, /*node_out=*/xo, /*edge_res=*/y, /*edge_out=*/yo);
    // conv2: edge_update on line graph (nodes = m = yo, edges = z)
    run_conv(S, 1, lidx, lidx + NE2, NE1, NE2, yo, z, bng2, bnb2,
             /*node_res=*/yo, /*node_out=*/yo, /*edge_res=*/z, /*edge_out=*/zo);
}

// round 13
// speedup vs baseline: 1.8858x; 1.1011x over previous
#include <cuda_runtime.h>
#include <cuda_fp16.h>
#include <cstdint>

#define F 128
static const int NN1 = 50000;   // nodes in g
static const int NE1 = 400000;  // edges in g == nodes of line graph
static const int NE2 = 800000;  // edges in line graph
#define MAXN 400000
#define MAXE 800000

// ---------------- scratch (device globals: no cudaMalloc allowed) ----------
__device__ __half  g_P[(size_t)MAXN * 512];      // [row][slot(4)][128] fp16 projections
__device__ __half  g_emsg[(size_t)MAXE * F];     // fp16 edge messages
__device__ float   g_h[(size_t)MAXN * F];
__device__ int     g_deg[MAXN];
__device__ int     g_starts[MAXN + 1];
__device__ int     g_cursor[MAXN];
__device__ int     g_elist[MAXE];
__device__ int     g_bsum[1024];
__device__ double  g_statsE[256];
__device__ double  g_statsN[256];
__device__ float   g_scaleE[F], g_shiftE[F], g_scaleN[F], g_shiftN[F];
__device__ __half  g_Whi[2 * 5 * 16384];         // swizzled fp16 weight images
__device__ __half  g_Wlo[2 * 5 * 16384];
__device__ float   g_biasR[2 * 5 * 128];

__device__ __forceinline__ float sigm(float v) { return 1.0f / (1.0f + __expf(-v)); }

__device__ __forceinline__ float4 h4_to_f4(uint2 u) {
    __half2 a = *(__half2*)&u.x, b = *(__half2*)&u.y;
    float2 fa = __half22float2(a), fb = __half22float2(b);
    return make_float4(fa.x, fa.y, fb.x, fb.y);
}
__device__ __forceinline__ uint2 f4_to_h4(float4 v) {
    __half2 a = __float22half2_rn(make_float2(v.x, v.y));
    __half2 b = __float22half2_rn(make_float2(v.z, v.w));
    uint2 u; u.x = *(uint32_t*)&a; u.y = *(uint32_t*)&b; return u;
}

__device__ __forceinline__ uint32_t smem_to_u32(const void* p) {
    uint32_t a;
    asm("{ .reg .u64 t; cvta.to.shared.u64 t, %1; cvt.u32.u64 %0, t; }"
        : "=r"(a) : "l"(p));
    return a;
}
__device__ __forceinline__ void cp16(uint32_t dst, const void* src) {
    asm volatile("cp.async.cg.shared.global [%0], [%1], 16;"
                 :: "r"(dst), "l"(src));
}
#define CP_COMMIT() asm volatile("cp.async.commit_group;")
#define CP_WAIT0()  asm volatile("cp.async.wait_group 0;")

#define LDSM_X4(r0, r1, r2, r3, a) \
    asm volatile("ldmatrix.sync.aligned.m8n8.x4.shared.b16 {%0,%1,%2,%3}, [%4];" \
                 : "=r"(r0), "=r"(r1), "=r"(r2), "=r"(r3) : "r"(a))
#define LDSM_X2(r0, r1, a) \
    asm volatile("ldmatrix.sync.aligned.m8n8.x2.shared.b16 {%0,%1}, [%2];" \
                 : "=r"(r0), "=r"(r1) : "r"(a))
#define MMA_F16(d, a0, a1, a2, a3, b0, b1) \
    asm volatile("mma.sync.aligned.m16n8k16.row.col.f32.f16.f16.f32 " \
                 "{%0,%1,%2,%3},{%4,%5,%6,%7},{%8,%9},{%0,%1,%2,%3};" \
                 : "+f"((d)[0]), "+f"((d)[1]), "+f"((d)[2]), "+f"((d)[3]) \
                 : "r"(a0), "r"(a1), "r"(a2), "r"(a3), "r"(b0), "r"(b1))

// XOR-swizzled fp16 image: row r (256B row), col k; 16B chunks xor'ed by (r&7).
__device__ __host__ __forceinline__ uint32_t sw_byte(int r, int k) {
    return (uint32_t)r * 256u + (uint32_t)(((k >> 3) ^ (r & 7)) << 4)
         + (uint32_t)((k & 7) << 1);
}

// ==================== weight prep: fp32 -> fp16 hi/lo swizzled images =======
__global__ void prep_weights(const float* __restrict__ W1, const float* __restrict__ b1,
                             const float* __restrict__ W2, const float* __restrict__ b2,
                             __half* __restrict__ Whi,
                             __half* __restrict__ Wlo,
                             float* __restrict__ biasR)
{
    int idx = blockIdx.x * blockDim.x + threadIdx.x;
    if (idx >= 2 * 5 * 16384) return;
    int c = idx / (5 * 16384);
    int rem = idx % (5 * 16384);
    int s = rem / 16384;
    int e = rem & 16383;
    int n = e >> 7, k = e & 127;
    const int map[5] = {0, 1, 3, 4, 2};   // slots: src_gate,dst_gate,src_upd,dst_upd | edge_gate
    const float* W = (c == 0 ? W1 : W2) + (size_t)map[s] * 16384;
    float a = W[n * 128 + k];
    __half h = __float2half_rn(a);
    __half l = __float2half_rn(a - __half2float(h));
    uint32_t off = sw_byte(n, k) >> 1;
    size_t base = (size_t)(c * 5 + s) * 16384;
    Whi[base + off] = h;
    Wlo[base + off] = l;
    if (e < 128) {
        const float* b = (c == 0 ? b1 : b2);
        biasR[(c * 5 + s) * 128 + e] = b[map[s] * 128 + e];
    }
}

// ==================== HMMA GEMM (256 thr, 8 warps, M=64 tile, 2 CTAs/SM) ====
// 2-pass fp16 split: A fp16, W = Whi + Wlo (fp16 each).
// node mode: out[r, s*128+c] = half(A[r] @ W_s^T + b_s)   (nW slots)
// edge mode (nW=1): emsg[e] = half(A[e]@W^T + b + P0[ei] + P1[ej]); BN stats.
// smem: A 16KB @0 | W_HI 32KB @16384 | W_LO 32KB @49152 | stats 1KB @81920.
// Edge phase 2 parks fp32 acc (32KB) at @16384 (W dead there).
static constexpr int GEMM_SMEM = 82944;

__global__ void __launch_bounds__(256, 2) gemm_mma(
    const float* __restrict__ A, int R,
    const __half* __restrict__ Whi, const __half* __restrict__ Wlo,
    const float* __restrict__ biasR, int nW,
    __half* __restrict__ out, int outStride,
    const int* __restrict__ ei, const int* __restrict__ ej,
    const __half* __restrict__ P, double* __restrict__ stats)
{
    extern __shared__ char smem[];
    const uint32_t sb   = smem_to_u32(smem);
    const uint32_t A_S  = sb;
    const uint32_t W_HI = sb + 16384, W_LO = sb + 49152;
    float* ssumS = (float*)(smem + 81920);   // [128]
    float* ssqS  = ssumS + 128;              // [128]
    const int tid = threadIdx.x, lane = tid & 31, wid = tid >> 5;
    const int warpM = wid & 1, warpN = wid >> 1; // warp tile 32m x 32n
    const int rowBase = blockIdx.x * 64;
    const bool EDGE = (ei != nullptr);

    if (EDGE && tid < 128) { ssumS[tid] = 0.f; ssqS[tid] = 0.f; }

    // prefetch W slot 0 (overlaps with A load/convert)
    {
        const float4* sh = (const float4*)Whi;
        const float4* sl = (const float4*)Wlo;
        #pragma unroll
        for (int u = 0; u < 8; u++) {
            int i = tid + u * 256;
            cp16(W_HI + (uint32_t)i * 16, sh + i);
            cp16(W_LO + (uint32_t)i * 16, sl + i);
        }
        CP_COMMIT();
    }

    // load + convert A tile (64 rows) into fp16 swizzled smem
    #pragma unroll
    for (int u = 0; u < 8; u++) {
        int idx = tid + u * 256;          // 0..2047 float4s
        int r = idx >> 5, q = idx & 31;   // row (0..63), k-float4
        float4 a = make_float4(0.f, 0.f, 0.f, 0.f);
        if (rowBase + r < R)
            a = ((const float4*)(A + (size_t)(rowBase + r) * 128))[q];
        uint2 hv = f4_to_h4(a);
        uint32_t off = (uint32_t)r * 256 + (uint32_t)((((q >> 1)) ^ (r & 7)) << 4)
                     + (uint32_t)((q & 1) << 3);
        *(uint2*)(smem + off) = hv;
    }

    // per-lane ldmatrix address components
    const int gA  = lane >> 3;
    const int rA  = (lane & 7) + ((gA & 1) << 3);
    const int kcA = gA >> 1;
    const int rB  = lane & 7;
    const int kcB = (lane >> 3) & 1;

    for (int s = 0; s < nW; s++) {
        if (s > 0) {
            __syncthreads();
            const float4* sh = (const float4*)(Whi + (size_t)s * 16384);
            const float4* sl = (const float4*)(Wlo + (size_t)s * 16384);
            #pragma unroll
            for (int u = 0; u < 8; u++) {
                int i = tid + u * 256;
                cp16(W_HI + (uint32_t)i * 16, sh + i);
                cp16(W_LO + (uint32_t)i * 16, sl + i);
            }
            CP_COMMIT();
        }
        CP_WAIT0();
        __syncthreads();

        float acc[2][4][4];
        #pragma unroll
        for (int mt = 0; mt < 2; mt++)
            #pragma unroll
            for (int nt = 0; nt < 4; nt++)
                #pragma unroll
                for (int i = 0; i < 4; i++) acc[mt][nt][i] = 0.f;

        #pragma unroll
        for (int ks = 0; ks < 8; ks++) {
            uint32_t ar[2][4], bh[4][2], bl[4][2];
            #pragma unroll
            for (int mt = 0; mt < 2; mt++) {
                int row = warpM * 32 + mt * 16 + rA;
                int kc  = ks * 2 + kcA;
                uint32_t off = (uint32_t)row * 256 + (uint32_t)((kc ^ (row & 7)) << 4);
                LDSM_X4(ar[mt][0], ar[mt][1], ar[mt][2], ar[mt][3], A_S + off);
            }
            #pragma unroll
            for (int nt = 0; nt < 4; nt++) {
                int row = warpN * 32 + nt * 8 + rB;
                int kc  = ks * 2 + kcB;
                uint32_t off = (uint32_t)row * 256 + (uint32_t)((kc ^ (row & 7)) << 4);
                LDSM_X2(bh[nt][0], bh[nt][1], W_HI + off);
                LDSM_X2(bl[nt][0], bl[nt][1], W_LO + off);
            }
            #pragma unroll
            for (int mt = 0; mt < 2; mt++)
                #pragma unroll
                for (int nt = 0; nt < 4; nt++) {
                    MMA_F16(acc[mt][nt], ar[mt][0], ar[mt][1], ar[mt][2], ar[mt][3],
                            bh[nt][0], bh[nt][1]);
                    MMA_F16(acc[mt][nt], ar[mt][0], ar[mt][1], ar[mt][2], ar[mt][3],
                            bl[nt][0], bl[nt][1]);
                }
        }

        if (!EDGE) {
            // node-mode epilogue: bias + fp16 store
            #pragma unroll
            for (int mt = 0; mt < 2; mt++) {
                int r0 = rowBase + warpM * 32 + mt * 16 + (lane >> 2);
                int r1 = r0 + 8;
                #pragma unroll
                for (int nt = 0; nt < 4; nt++) {
                    int c = warpN * 32 + nt * 8 + ((lane & 3) << 1);
                    float bx = __ldg(biasR + s * 128 + c);
                    float by = __ldg(biasR + s * 128 + c + 1);
                    if (r0 < R) {
                        __half2 v = __float22half2_rn(
                            make_float2(acc[mt][nt][0] + bx, acc[mt][nt][1] + by));
                        *(__half2*)(out + (size_t)r0 * outStride + s * 128 + c) = v;
                    }
                    if (r1 < R) {
                        __half2 v = __float22half2_rn(
                            make_float2(acc[mt][nt][2] + bx, acc[mt][nt][3] + by));
                        *(__half2*)(out + (size_t)r1 * outStride + s * 128 + c) = v;
                    }
                }
            }
        } else {
            // edge-mode: park acc in smem over the dead W region, warp-per-edge
            __syncthreads();   // all warps done with LDSM reads of W
            char* park = smem + 16384;
            #pragma unroll
            for (int mt = 0; mt < 2; mt++) {
                int rl0 = warpM * 32 + mt * 16 + (lane >> 2);
                #pragma unroll
                for (int nt = 0; nt < 4; nt++) {
                    int c = warpN * 32 + nt * 8 + ((lane & 3) << 1);
                    *(float2*)(park + (size_t)rl0 * 512 + c * 4) =
                        make_float2(acc[mt][nt][0], acc[mt][nt][1]);
                    *(float2*)(park + (size_t)(rl0 + 8) * 512 + c * 4) =
                        make_float2(acc[mt][nt][2], acc[mt][nt][3]);
                }
            }
            __syncthreads();

            // phase 2: warp w handles edges rowBase + w*8 .. +7 (coalesced)
            const float4 b4 = ((const float4*)biasR)[lane];
            float4 lsum = make_float4(0.f, 0.f, 0.f, 0.f);
            float4 lsq  = make_float4(0.f, 0.f, 0.f, 0.f);
            int idx_i[8], idx_j[8];
            #pragma unroll
            for (int u = 0; u < 8; u++) {
                int e = rowBase + wid * 8 + u;
                idx_i[u] = __ldg(ei + e);
                idx_j[u] = __ldg(ej + e);
            }
            const uint2* Pu = (const uint2*)P;   // row stride 128 uint2
            #pragma unroll
            for (int u = 0; u < 8; u++) {
                int r = wid * 8 + u;
                int e = rowBase + r;
                float4 a  = *(const float4*)(park + (size_t)r * 512 + lane * 16);
                float4 p0 = h4_to_f4(__ldg(Pu + (size_t)idx_i[u] * 128 + lane));
                float4 p1 = h4_to_f4(__ldg(Pu + (size_t)idx_j[u] * 128 + 32 + lane));
                float4 v = make_float4(a.x + b4.x + p0.x + p1.x,
                                       a.y + b4.y + p0.y + p1.y,
                                       a.z + b4.z + p0.z + p1.z,
                                       a.w + b4.w + p0.w + p1.w);
                ((uint2*)(out + (size_t)e * outStride))[lane] = f4_to_h4(v);
                lsum.x += v.x; lsum.y += v.y; lsum.z += v.z; lsum.w += v.w;
                lsq.x += v.x * v.x; lsq.y += v.y * v.y;
                lsq.z += v.z * v.z; lsq.w += v.w * v.w;
            }
            atomicAdd(&ssumS[lane * 4 + 0], lsum.x);
            atomicAdd(&ssumS[lane * 4 + 1], lsum.y);
            atomicAdd(&ssumS[lane * 4 + 2], lsum.z);
            atomicAdd(&ssumS[lane * 4 + 3], lsum.w);
            atomicAdd(&ssqS[lane * 4 + 0], lsq.x);
            atomicAdd(&ssqS[lane * 4 + 1], lsq.y);
            atomicAdd(&ssqS[lane * 4 + 2], lsq.z);
            atomicAdd(&ssqS[lane * 4 + 3], lsq.w);
            __syncthreads();
            if (tid < 128) {
                atomicAdd(&stats[tid],       (double)ssumS[tid]);
                atomicAdd(&stats[128 + tid], (double)ssqS[tid]);
            }
        }
    }
}

// ---------------- CSR build ------------------------------------------------
__global__ void hist_deg(const int* __restrict__ ei, int* __restrict__ deg, int E)
{
    for (int e = blockIdx.x * blockDim.x + threadIdx.x; e < E;
         e += gridDim.x * blockDim.x)
        atomicAdd(&deg[ei[e]], 1);
}

__global__ void scan1(const int* __restrict__ in, int* __restrict__ out,
                      int* __restrict__ bsum, int n)
{
    __shared__ int s[1024];
    int i = blockIdx.x * 1024 + threadIdx.x;
    int v = (i < n) ? in[i] : 0;
    s[threadIdx.x] = v;
    __syncthreads();
    for (int off = 1; off < 1024; off <<= 1) {
        int t = (threadIdx.x >= off) ? s[threadIdx.x - off] : 0;
        __syncthreads();
        s[threadIdx.x] += t;
        __syncthreads();
    }
    if (i < n) out[i] = s[threadIdx.x] - v;
    if (threadIdx.x == 1023) bsum[blockIdx.x] = s[1023];
}

__global__ void scan2(int* __restrict__ bsum, int nb)
{
    __shared__ int s[1024];
    int v = (threadIdx.x < nb) ? bsum[threadIdx.x] : 0;
    s[threadIdx.x] = v;
    __syncthreads();
    for (int off = 1; off < 1024; off <<= 1) {
        int t = (threadIdx.x >= off) ? s[threadIdx.x - off] : 0;
        __syncthreads();
        s[threadIdx.x] += t;
        __syncthreads();
    }
    if (threadIdx.x < nb) bsum[threadIdx.x] = s[threadIdx.x] - v;
}

__global__ void scan3(int* __restrict__ out, const int* __restrict__ bsum,
                      int n, int total)
{
    int i = blockIdx.x * 1024 + threadIdx.x;
    if (i < n) out[i] += bsum[blockIdx.x];
    if (blockIdx.x == 0 && threadIdx.x == 0) out[n] = total;
}

__global__ void scatter_edges(const int* __restrict__ ei,
                              const int* __restrict__ starts,
                              int* __restrict__ cursor, int* __restrict__ elist, int E)
{
    for (int e = blockIdx.x * blockDim.x + threadIdx.x; e < E;
         e += gridDim.x * blockDim.x) {
        int n = ei[e];
        int p = atomicAdd(&cursor[n], 1);
        elist[starts[n] + p] = e;
    }
}

// ------- per-node aggregation + fused edge BN/silu/residual -----------------
__global__ void __launch_bounds__(256) node_agg(
    const int* __restrict__ starts, const int* __restrict__ elist,
    const int* __restrict__ ej, const __half* __restrict__ emsg,
    const __half* __restrict__ P,
    float* __restrict__ h, int nN, double* __restrict__ stats,
    const float* __restrict__ scaleE, const float* __restrict__ shiftE,
    const float* __restrict__ eres, float* __restrict__ eout)
{
    __shared__ float ssum[128], ssq[128];
    if (threadIdx.x < 128) { ssum[threadIdx.x] = 0.f; ssq[threadIdx.x] = 0.f; }
    __syncthreads();
    const int lane  = threadIdx.x & 31;
    const int warp  = (blockIdx.x * blockDim.x + threadIdx.x) >> 5;
    const int nwarp = (gridDim.x * blockDim.x) >> 5;
    const float4 scE = ((const float4*)scaleE)[lane];
    const float4 shE = ((const float4*)shiftE)[lane];
    const uint2* Eu = (const uint2*)emsg;   // row stride 32 uint2
    const uint2* Pu = (const uint2*)P;      // row stride 128 uint2
    float4 ls = make_float4(0.f, 0.f, 0.f, 0.f);
    float4 lq = make_float4(0.f, 0.f, 0.f, 0.f);
    for (int n = warp; n < nN; n += nwarp) {
        int s = starts[n], t = starts[n + 1];
        float4 sg = make_float4(0.f, 0.f, 0.f, 0.f);
        float4 sn = make_float4(0.f, 0.f, 0.f, 0.f);
        for (int k = s; k < t; k++) {
            int e = elist[k];
            int j = ej[e];
            float4 v  = h4_to_f4(__ldg(Eu + (size_t)e * 32 + lane));
            float4 sig = make_float4(sigm(v.x), sigm(v.y), sigm(v.z), sigm(v.w));
            float4 p4 = h4_to_f4(__ldg(Pu + (size_t)j * 128 + 96 + lane));
            sg.x += sig.x; sg.y += sig.y; sg.z += sig.z; sg.w += sig.w;
            sn.x += sig.x * p4.x; sn.y += sig.y * p4.y;
            sn.z += sig.z * p4.z; sn.w += sig.w * p4.w;
            // fused edge update: eout = silu(bn(v)) + eres
            float4 b = make_float4(v.x * scE.x + shE.x, v.y * scE.y + shE.y,
                                   v.z * scE.z + shE.z, v.w * scE.w + shE.w);
            float4 er = ((const float4*)eres)[(long long)e * 32 + lane];
            float4 eo = make_float4(b.x * sigm(b.x) + er.x, b.y * sigm(b.y) + er.y,
                                    b.z * sigm(b.z) + er.z, b.w * sigm(b.w) + er.w);
            ((float4*)eout)[(long long)e * 32 + lane] = eo;
        }
        float4 hv = h4_to_f4(__ldg(Pu + (size_t)n * 128 + 64 + lane));
        hv.x += sn.x / (sg.x + 1e-9f); hv.y += sn.y / (sg.y + 1e-9f);
        hv.z += sn.z / (sg.z + 1e-9f); hv.w += sn.w / (sg.w + 1e-9f);
        ((float4*)h)[(long long)n * 32 + lane] = hv;
        ls.x += hv.x; ls.y += hv.y; ls.z += hv.z; ls.w += hv.w;
        lq.x += hv.x * hv.x; lq.y += hv.y * hv.y;
        lq.z += hv.z * hv.z; lq.w += hv.w * hv.w;
    }
    atomicAdd(&ssum[lane * 4 + 0], ls.x); atomicAdd(&ssum[lane * 4 + 1], ls.y);
    atomicAdd(&ssum[lane * 4 + 2], ls.z); atomicAdd(&ssum[lane * 4 + 3], ls.w);
    atomicAdd(&ssq[lane * 4 + 0], lq.x);  atomicAdd(&ssq[lane * 4 + 1], lq.y);
    atomicAdd(&ssq[lane * 4 + 2], lq.z);  atomicAdd(&ssq[lane * 4 + 3], lq.w);
    __syncthreads();
    if (threadIdx.x < 128) {
        atomicAdd(&stats[threadIdx.x],       (double)ssum[threadIdx.x]);
        atomicAdd(&stats[128 + threadIdx.x], (double)ssq[threadIdx.x]);
    }
}

// ---------------- BN finalize + fused apply ---------------------------------
__global__ void finalize_bn(const double* __restrict__ stats,
                            const float* __restrict__ gamma,
                            const float* __restrict__ beta,
                            double invR, float* __restrict__ scale,
                            float* __restrict__ shift)
{
    int f = threadIdx.x;
    double mu  = stats[f] * invR;
    double var = stats[128 + f] * invR - mu * mu;
    float inv = rsqrtf((float)var + 1e-5f);
    float s = gamma[f] * inv;
    scale[f] = s;
    shift[f] = beta[f] - s * (float)mu;
}

__global__ void apply_bn_silu_res(const float* __restrict__ hbuf,
                                  const float* __restrict__ res,
                                  const float* __restrict__ scale,
                                  const float* __restrict__ shift,
                                  float* __restrict__ out, long long n4)
{
    for (long long idx = (long long)blockIdx.x * blockDim.x + threadIdx.x;
         idx < n4; idx += (long long)gridDim.x * blockDim.x) {
        int l = (int)(idx & 31);
        float4 sc = ((const float4*)scale)[l];
        float4 sh = ((const float4*)shift)[l];
        float4 v = ((const float4*)hbuf)[idx];
        v.x = v.x * sc.x + sh.x; v.y = v.y * sc.y + sh.y;
        v.z = v.z * sc.z + sh.z; v.w = v.w * sc.w + sh.w;
        float4 u = make_float4(v.x * sigm(v.x), v.y * sigm(v.y),
                               v.z * sigm(v.z), v.w * sigm(v.w));
        float4 r = ((const float4*)res)[idx];
        u.x += r.x; u.y += r.y; u.z += r.z; u.w += r.w;
        ((float4*)out)[idx] = u;
    }
}

// ---------------- host orchestration ----------------------------------------
struct Scratch {
    __half *P, *emsg;
    float *h;
    int *deg, *starts, *cursor, *elist, *bsum;
    double *statsE, *statsN;
    float *scaleE, *shiftE, *scaleN, *shiftN;
    __half *Whi, *Wlo;
    float *biasR;
};

static void run_conv(const Scratch& S, int conv,
                     const int* ei, const int* ej, int nN, int E,
                     const float* xnode, const float* eedge,
                     const float* bng, const float* bnb,
                     const float* node_res, float* node_out,
                     const float* edge_res, float* edge_out)
{
    cudaStream_t st = 0;
    cudaMemsetAsync(S.deg, 0, (size_t)nN * sizeof(int), st);
    cudaMemsetAsync(S.cursor, 0, (size_t)nN * sizeof(int), st);
    cudaMemsetAsync(S.statsE, 0, 256 * sizeof(double), st);
    cudaMemsetAsync(S.statsN, 0, 256 * sizeof(double), st);

    int gbN = (nN + 63) / 64;
    int gbE = (E + 63) / 64;
    const __half* Whi = S.Whi + (size_t)conv * 5 * 16384;
    const __half* Wlo = S.Wlo + (size_t)conv * 5 * 16384;
    const float* biasR = S.biasR + conv * 5 * 128;

    // CSR (independent)
    hist_deg<<<2048, 256, 0, st>>>(ei, S.deg, E);
    int nb = (nN + 1023) / 1024;
    scan1<<<nb, 1024, 0, st>>>(S.deg, S.starts, S.bsum, nN);
    scan2<<<1, 1024, 0, st>>>(S.bsum, nb);
    scan3<<<nb, 1024, 0, st>>>(S.starts, S.bsum, nN, E);
    scatter_edges<<<2048, 256, 0, st>>>(ei, S.starts, S.cursor, S.elist, E);

    // fused node projections (slots 0..3 -> P, fp16)
    gemm_mma<<<gbN, 256, GEMM_SMEM, st>>>(xnode, nN, Whi, Wlo, biasR, 4,
                                          S.P, 512, nullptr, nullptr, nullptr,
                                          nullptr);
    // edge projection + phase-2 fused gather-add + BN stats -> emsg (fp16)
    gemm_mma<<<gbE, 256, GEMM_SMEM, st>>>(eedge, E, Whi + 4 * 16384, Wlo + 4 * 16384,
                                          biasR + 4 * 128, 1, S.emsg, 128,
                                          ei, ej, S.P, S.statsE);
    finalize_bn<<<1, 128, 0, st>>>(S.statsE, bng + 0 * 128, bnb + 0 * 128,
                                   1.0 / (double)E, S.scaleE, S.shiftE);

    // node aggregation + node BN stats + fused edge BN/silu/residual output
    node_agg<<<4096, 256, 0, st>>>(S.starts, S.elist, ej, S.emsg, S.P,
                                   S.h, nN, S.statsN,
                                   S.scaleE, S.shiftE, edge_res, edge_out);
    finalize_bn<<<1, 128, 0, st>>>(S.statsN, bng + 1 * 128, bnb + 1 * 128,
                                   1.0 / (double)nN, S.scaleN, S.shiftN);

    long long n4n = (long long)nN * 32;
    int gbA = (int)((n4n + 255) / 256); if (gbA > 8192) gbA = 8192;
    apply_bn_silu_res<<<gbA, 256, 0, st>>>(S.h, node_res, S.scaleN, S.shiftN,
                                           node_out, n4n);
}

extern "C" void kernel_launch(void* const* d_in, const int* in_sizes, int n_in,
                              void* d_out, int out_size)
{
    const int*   gidx = (const int*)d_in[0];
    const int*   lidx = (const int*)d_in[1];
    const float* x    = (const float*)d_in[2];
    const float* y    = (const float*)d_in[3];
    const float* z    = (const float*)d_in[4];
    const float* W1   = (const float*)d_in[5];
    const float* b1   = (const float*)d_in[6];
    const float* bng1 = (const float*)d_in[7];
    const float* bnb1 = (const float*)d_in[8];
    const float* W2   = (const float*)d_in[9];
    const float* b2   = (const float*)d_in[10];
    const float* bng2 = (const float*)d_in[11];
    const float* bnb2 = (const float*)d_in[12];

    float* xo = (float*)d_out;
    float* yo = xo + (long long)NN1 * F;
    float* zo = yo + (long long)NE1 * F;

    Scratch S;
    cudaGetSymbolAddress((void**)&S.P, g_P);
    cudaGetSymbolAddress((void**)&S.emsg, g_emsg);
    cudaGetSymbolAddress((void**)&S.h, g_h);
    cudaGetSymbolAddress((void**)&S.deg, g_deg);
    cudaGetSymbolAddress((void**)&S.starts, g_starts);
    cudaGetSymbolAddress((void**)&S.cursor, g_cursor);
    cudaGetSymbolAddress((void**)&S.elist, g_elist);
    cudaGetSymbolAddress((void**)&S.bsum, g_bsum);
    cudaGetSymbolAddress((void**)&S.statsE, g_statsE);
    cudaGetSymbolAddress((void**)&S.statsN, g_statsN);
    cudaGetSymbolAddress((void**)&S.scaleE, g_scaleE);
    cudaGetSymbolAddress((void**)&S.shiftE, g_shiftE);
    cudaGetSymbolAddress((void**)&S.scaleN, g_scaleN);
    cudaGetSymbolAddress((void**)&S.shiftN, g_shiftN);
    cudaGetSymbolAddress((void**)&S.Whi, g_Whi);
    cudaGetSymbolAddress((void**)&S.Wlo, g_Wlo);
    cudaGetSymbolAddress((void**)&S.biasR, g_biasR);

    cudaFuncSetAttribute(gemm_mma, cudaFuncAttributeMaxDynamicSharedMemorySize,
                         GEMM_SMEM);

    prep_weights<<<(2 * 5 * 16384 + 255) / 256, 256>>>(W1, b1, W2, b2,
                                                       S.Whi, S.Wlo, S.biasR);

    // conv1: node_update on g
    run_conv(S, 0, gidx, gidx + NE1, NN1, NE1, x, y, bng1, bnb1,
             /*node_res=*/x, /*node_out=*/xo, /*edge_res=*/y, /*edge_out=*/yo);
    // conv2: edge_update on line graph (nodes = m = yo, edges = z)
    run_conv(S, 1, lidx, lidx + NE2, NE1, NE2, yo, z, bng2, bnb2,
             /*node_res=*/yo, /*node_out=*/yo, /*edge_res=*/z, /*edge_out=*/zo);
}

// round 15
// speedup vs baseline: 1.8876x; 1.0009x over previous
#include <cuda_runtime.h>
#include <cuda_fp16.h>
#include <cstdint>

#define F 128
static const int NN1 = 50000;   // nodes in g
static const int NE1 = 400000;  // edges in g == nodes of line graph
static const int NE2 = 800000;  // edges in line graph
#define MAXN 400000
#define MAXE 800000

// ---------------- scratch (device globals: no cudaMalloc allowed) ----------
__device__ __half  g_P[(size_t)MAXN * 512];      // [row][slot(4)][128] fp16 projections
__device__ __half  g_emsg[(size_t)MAXE * F];     // fp16 edge messages
__device__ float   g_h[(size_t)MAXN * F];
__device__ int     g_deg[MAXN];
__device__ int     g_starts[MAXN + 1];
__device__ int     g_cursor[MAXN];
__device__ int     g_elist[MAXE];
__device__ int     g_bsum[1024];
__device__ double  g_statsE[256];
__device__ double  g_statsN[256];
__device__ float   g_scaleE[F], g_shiftE[F], g_scaleN[F], g_shiftN[F];
__device__ __half  g_Whi[2 * 5 * 16384];         // swizzled fp16 weight images
__device__ __half  g_Wlo[2 * 5 * 16384];
__device__ float   g_biasR[2 * 5 * 128];

__device__ __forceinline__ float sigm(float v) { return 1.0f / (1.0f + __expf(-v)); }

__device__ __forceinline__ float4 h4_to_f4(uint2 u) {
    __half2 a = *(__half2*)&u.x, b = *(__half2*)&u.y;
    float2 fa = __half22float2(a), fb = __half22float2(b);
    return make_float4(fa.x, fa.y, fb.x, fb.y);
}
__device__ __forceinline__ uint2 f4_to_h4(float4 v) {
    __half2 a = __float22half2_rn(make_float2(v.x, v.y));
    __half2 b = __float22half2_rn(make_float2(v.z, v.w));
    uint2 u; u.x = *(uint32_t*)&a; u.y = *(uint32_t*)&b; return u;
}

__device__ __forceinline__ uint32_t smem_to_u32(const void* p) {
    uint32_t a;
    asm("{ .reg .u64 t; cvta.to.shared.u64 t, %1; cvt.u32.u64 %0, t; }"
        : "=r"(a) : "l"(p));
    return a;
}
__device__ __forceinline__ void cp16(uint32_t dst, const void* src) {
    asm volatile("cp.async.cg.shared.global [%0], [%1], 16;"
                 :: "r"(dst), "l"(src));
}
#define CP_COMMIT() asm volatile("cp.async.commit_group;")
#define CP_WAIT0()  asm volatile("cp.async.wait_group 0;")

#define LDSM_X4(r0, r1, r2, r3, a) \
    asm volatile("ldmatrix.sync.aligned.m8n8.x4.shared.b16 {%0,%1,%2,%3}, [%4];" \
                 : "=r"(r0), "=r"(r1), "=r"(r2), "=r"(r3) : "r"(a))
#define LDSM_X2(r0, r1, a) \
    asm volatile("ldmatrix.sync.aligned.m8n8.x2.shared.b16 {%0,%1}, [%2];" \
                 : "=r"(r0), "=r"(r1) : "r"(a))
#define MMA_F16(d, a0, a1, a2, a3, b0, b1) \
    asm volatile("mma.sync.aligned.m16n8k16.row.col.f32.f16.f16.f32 " \
                 "{%0,%1,%2,%3},{%4,%5,%6,%7},{%8,%9},{%0,%1,%2,%3};" \
                 : "+f"((d)[0]), "+f"((d)[1]), "+f"((d)[2]), "+f"((d)[3]) \
                 : "r"(a0), "r"(a1), "r"(a2), "r"(a3), "r"(b0), "r"(b1))

// XOR-swizzled fp16 image: row r (256B row), col k; 16B chunks xor'ed by (r&7).
__device__ __host__ __forceinline__ uint32_t sw_byte(int r, int k) {
    return (uint32_t)r * 256u + (uint32_t)(((k >> 3) ^ (r & 7)) << 4)
         + (uint32_t)((k & 7) << 1);
}

// ==================== weight prep: fp32 -> fp16 hi/lo swizzled images =======
__global__ void prep_weights(const float* __restrict__ W1, const float* __restrict__ b1,
                             const float* __restrict__ W2, const float* __restrict__ b2,
                             __half* __restrict__ Whi,
                             __half* __restrict__ Wlo,
                             float* __restrict__ biasR)
{
    int idx = blockIdx.x * blockDim.x + threadIdx.x;
    if (idx >= 2 * 5 * 16384) return;
    int c = idx / (5 * 16384);
    int rem = idx % (5 * 16384);
    int s = rem / 16384;
    int e = rem & 16383;
    int n = e >> 7, k = e & 127;
    const int map[5] = {0, 1, 3, 4, 2};   // slots: src_gate,dst_gate,src_upd,dst_upd | edge_gate
    const float* W = (c == 0 ? W1 : W2) + (size_t)map[s] * 16384;
    float a = W[n * 128 + k];
    __half h = __float2half_rn(a);
    __half l = __float2half_rn(a - __half2float(h));
    uint32_t off = sw_byte(n, k) >> 1;
    size_t base = (size_t)(c * 5 + s) * 16384;
    Whi[base + off] = h;
    Wlo[base + off] = l;
    if (e < 128) {
        const float* b = (c == 0 ? b1 : b2);
        biasR[(c * 5 + s) * 128 + e] = b[map[s] * 128 + e];
    }
}

// ==================== HMMA GEMM (256 thr, 8 warps, M=64 tile, 2 CTAs/SM) ====
// 2-pass fp16 split: A fp16, W = Whi + Wlo (fp16 each).
// node mode: out[r, s*128+c] = half(A[r] @ W_s^T + b_s)   (nW slots)
// edge mode (nW=1): emsg[e] = half(A[e]@W^T + b + P0[ei] + P1[ej]); BN stats.
// smem: A 16KB @0 | W_HI 32KB @16384 | W_LO 32KB @49152 | stats 1KB @81920.
// Edge phase 2 parks fp32 acc (32KB) at @16384 (W dead there).
static constexpr int GEMM_SMEM = 82944;

__global__ void __launch_bounds__(256, 2) gemm_mma(
    const float* __restrict__ A, int R,
    const __half* __restrict__ Whi, const __half* __restrict__ Wlo,
    const float* __restrict__ biasR, int nW,
    __half* __restrict__ out, int outStride,
    const int* __restrict__ ei, const int* __restrict__ ej,
    const __half* __restrict__ P, double* __restrict__ stats)
{
    extern __shared__ char smem[];
    const uint32_t sb   = smem_to_u32(smem);
    const uint32_t A_S  = sb;
    const uint32_t W_HI = sb + 16384, W_LO = sb + 49152;
    float* ssumS = (float*)(smem + 81920);   // [128]
    float* ssqS  = ssumS + 128;              // [128]
    const int tid = threadIdx.x, lane = tid & 31, wid = tid >> 5;
    const int warpM = wid & 1, warpN = wid >> 1; // warp tile 32m x 32n
    const int rowBase = blockIdx.x * 64;
    const bool EDGE = (ei != nullptr);

    if (EDGE && tid < 128) { ssumS[tid] = 0.f; ssqS[tid] = 0.f; }

    // prefetch W slot 0 (overlaps with A load/convert)
    {
        const float4* sh = (const float4*)Whi;
        const float4* sl = (const float4*)Wlo;
        #pragma unroll
        for (int u = 0; u < 8; u++) {
            int i = tid + u * 256;
            cp16(W_HI + (uint32_t)i * 16, sh + i);
            cp16(W_LO + (uint32_t)i * 16, sl + i);
        }
        CP_COMMIT();
    }

    // load + convert A tile (64 rows) into fp16 swizzled smem
    #pragma unroll
    for (int u = 0; u < 8; u++) {
        int idx = tid + u * 256;          // 0..2047 float4s
        int r = idx >> 5, q = idx & 31;   // row (0..63), k-float4
        float4 a = make_float4(0.f, 0.f, 0.f, 0.f);
        if (rowBase + r < R)
            a = ((const float4*)(A + (size_t)(rowBase + r) * 128))[q];
        uint2 hv = f4_to_h4(a);
        uint32_t off = (uint32_t)r * 256 + (uint32_t)((((q >> 1)) ^ (r & 7)) << 4)
                     + (uint32_t)((q & 1) << 3);
        *(uint2*)(smem + off) = hv;
    }

    // per-lane ldmatrix address components
    const int gA  = lane >> 3;
    const int rA  = (lane & 7) + ((gA & 1) << 3);
    const int kcA = gA >> 1;
    const int rB  = lane & 7;
    const int kcB = (lane >> 3) & 1;

    for (int s = 0; s < nW; s++) {
        if (s > 0) {
            __syncthreads();
            const float4* sh = (const float4*)(Whi + (size_t)s * 16384);
            const float4* sl = (const float4*)(Wlo + (size_t)s * 16384);
            #pragma unroll
            for (int u = 0; u < 8; u++) {
                int i = tid + u * 256;
                cp16(W_HI + (uint32_t)i * 16, sh + i);
                cp16(W_LO + (uint32_t)i * 16, sl + i);
            }
            CP_COMMIT();
        }
        CP_WAIT0();
        __syncthreads();

        float acc[2][4][4];
        #pragma unroll
        for (int mt = 0; mt < 2; mt++)
            #pragma unroll
            for (int nt = 0; nt < 4; nt++)
                #pragma unroll
                for (int i = 0; i < 4; i++) acc[mt][nt][i] = 0.f;

        #pragma unroll
        for (int ks = 0; ks < 8; ks++) {
            uint32_t ar[2][4], bh[4][2], bl[4][2];
            #pragma unroll
            for (int mt = 0; mt < 2; mt++) {
                int row = warpM * 32 + mt * 16 + rA;
                int kc  = ks * 2 + kcA;
                uint32_t off = (uint32_t)row * 256 + (uint32_t)((kc ^ (row & 7)) << 4);
                LDSM_X4(ar[mt][0], ar[mt][1], ar[mt][2], ar[mt][3], A_S + off);
            }
            #pragma unroll
            for (int nt = 0; nt < 4; nt++) {
                int row = warpN * 32 + nt * 8 + rB;
                int kc  = ks * 2 + kcB;
                uint32_t off = (uint32_t)row * 256 + (uint32_t)((kc ^ (row & 7)) << 4);
                LDSM_X2(bh[nt][0], bh[nt][1], W_HI + off);
                LDSM_X2(bl[nt][0], bl[nt][1], W_LO + off);
            }
            #pragma unroll
            for (int mt = 0; mt < 2; mt++)
                #pragma unroll
                for (int nt = 0; nt < 4; nt++) {
                    MMA_F16(acc[mt][nt], ar[mt][0], ar[mt][1], ar[mt][2], ar[mt][3],
                            bh[nt][0], bh[nt][1]);
                    MMA_F16(acc[mt][nt], ar[mt][0], ar[mt][1], ar[mt][2], ar[mt][3],
                            bl[nt][0], bl[nt][1]);
                }
        }

        if (!EDGE) {
            // node-mode epilogue: bias + fp16 store
            #pragma unroll
            for (int mt = 0; mt < 2; mt++) {
                int r0 = rowBase + warpM * 32 + mt * 16 + (lane >> 2);
                int r1 = r0 + 8;
                #pragma unroll
                for (int nt = 0; nt < 4; nt++) {
                    int c = warpN * 32 + nt * 8 + ((lane & 3) << 1);
                    float bx = __ldg(biasR + s * 128 + c);
                    float by = __ldg(biasR + s * 128 + c + 1);
                    if (r0 < R) {
                        __half2 v = __float22half2_rn(
                            make_float2(acc[mt][nt][0] + bx, acc[mt][nt][1] + by));
                        *(__half2*)(out + (size_t)r0 * outStride + s * 128 + c) = v;
                    }
                    if (r1 < R) {
                        __half2 v = __float22half2_rn(
                            make_float2(acc[mt][nt][2] + bx, acc[mt][nt][3] + by));
                        *(__half2*)(out + (size_t)r1 * outStride + s * 128 + c) = v;
                    }
                }
            }
        } else {
            // edge-mode: park acc in smem over the dead W region, warp-per-edge
            __syncthreads();   // all warps done with LDSM reads of W
            char* park = smem + 16384;
            #pragma unroll
            for (int mt = 0; mt < 2; mt++) {
                int rl0 = warpM * 32 + mt * 16 + (lane >> 2);
                #pragma unroll
                for (int nt = 0; nt < 4; nt++) {
                    int c = warpN * 32 + nt * 8 + ((lane & 3) << 1);
                    *(float2*)(park + (size_t)rl0 * 512 + c * 4) =
                        make_float2(acc[mt][nt][0], acc[mt][nt][1]);
                    *(float2*)(park + (size_t)(rl0 + 8) * 512 + c * 4) =
                        make_float2(acc[mt][nt][2], acc[mt][nt][3]);
                }
            }
            __syncthreads();

            // phase 2: warp w handles edges rowBase + w*8 .. +7 (coalesced)
            const float4 b4 = ((const float4*)biasR)[lane];
            float4 lsum = make_float4(0.f, 0.f, 0.f, 0.f);
            float4 lsq  = make_float4(0.f, 0.f, 0.f, 0.f);
            int idx_i[8], idx_j[8];
            #pragma unroll
            for (int u = 0; u < 8; u++) {
                int e = rowBase + wid * 8 + u;
                idx_i[u] = __ldg(ei + e);
                idx_j[u] = __ldg(ej + e);
            }
            const uint2* Pu = (const uint2*)P;   // row stride 128 uint2
            #pragma unroll
            for (int u = 0; u < 8; u++) {
                int r = wid * 8 + u;
                int e = rowBase + r;
                float4 a  = *(const float4*)(park + (size_t)r * 512 + lane * 16);
                float4 p0 = h4_to_f4(__ldg(Pu + (size_t)idx_i[u] * 128 + lane));
                float4 p1 = h4_to_f4(__ldg(Pu + (size_t)idx_j[u] * 128 + 32 + lane));
                float4 v = make_float4(a.x + b4.x + p0.x + p1.x,
                                       a.y + b4.y + p0.y + p1.y,
                                       a.z + b4.z + p0.z + p1.z,
                                       a.w + b4.w + p0.w + p1.w);
                ((uint2*)(out + (size_t)e * outStride))[lane] = f4_to_h4(v);
                lsum.x += v.x; lsum.y += v.y; lsum.z += v.z; lsum.w += v.w;
                lsq.x += v.x * v.x; lsq.y += v.y * v.y;
                lsq.z += v.z * v.z; lsq.w += v.w * v.w;
            }
            atomicAdd(&ssumS[lane * 4 + 0], lsum.x);
            atomicAdd(&ssumS[lane * 4 + 1], lsum.y);
            atomicAdd(&ssumS[lane * 4 + 2], lsum.z);
            atomicAdd(&ssumS[lane * 4 + 3], lsum.w);
            atomicAdd(&ssqS[lane * 4 + 0], lsq.x);
            atomicAdd(&ssqS[lane * 4 + 1], lsq.y);
            atomicAdd(&ssqS[lane * 4 + 2], lsq.z);
            atomicAdd(&ssqS[lane * 4 + 3], lsq.w);
            __syncthreads();
            if (tid < 128) {
                atomicAdd(&stats[tid],       (double)ssumS[tid]);
                atomicAdd(&stats[128 + tid], (double)ssqS[tid]);
            }
        }
    }
}

// ---------------- CSR build ------------------------------------------------
__global__ void hist_deg(const int* __restrict__ ei, int* __restrict__ deg, int E)
{
    for (int e = blockIdx.x * blockDim.x + threadIdx.x; e < E;
         e += gridDim.x * blockDim.x)
        atomicAdd(&deg[ei[e]], 1);
}

__global__ void scan1(const int* __restrict__ in, int* __restrict__ out,
                      int* __restrict__ bsum, int n)
{
    __shared__ int s[1024];
    int i = blockIdx.x * 1024 + threadIdx.x;
    int v = (i < n) ? in[i] : 0;
    s[threadIdx.x] = v;
    __syncthreads();
    for (int off = 1; off < 1024; off <<= 1) {
        int t = (threadIdx.x >= off) ? s[threadIdx.x - off] : 0;
        __syncthreads();
        s[threadIdx.x] += t;
        __syncthreads();
    }
    if (i < n) out[i] = s[threadIdx.x] - v;
    if (threadIdx.x == 1023) bsum[blockIdx.x] = s[1023];
}

__global__ void scan2(int* __restrict__ bsum, int nb)
{
    __shared__ int s[1024];
    int v = (threadIdx.x < nb) ? bsum[threadIdx.x] : 0;
    s[threadIdx.x] = v;
    __syncthreads();
    for (int off = 1; off < 1024; off <<= 1) {
        int t = (threadIdx.x >= off) ? s[threadIdx.x - off] : 0;
        __syncthreads();
        s[threadIdx.x] += t;
        __syncthreads();
    }
    if (threadIdx.x < nb) bsum[threadIdx.x] = s[threadIdx.x] - v;
}

__global__ void scan3(int* __restrict__ out, const int* __restrict__ bsum,
                      int n, int total)
{
    int i = blockIdx.x * 1024 + threadIdx.x;
    if (i < n) out[i] += bsum[blockIdx.x];
    if (blockIdx.x == 0 && threadIdx.x == 0) out[n] = total;
}

__global__ void scatter_edges(const int* __restrict__ ei,
                              const int* __restrict__ starts,
                              int* __restrict__ cursor, int* __restrict__ elist, int E)
{
    for (int e = blockIdx.x * blockDim.x + threadIdx.x; e < E;
         e += gridDim.x * blockDim.x) {
        int n = ei[e];
        int p = atomicAdd(&cursor[n], 1);
        elist[starts[n] + p] = e;
    }
}

// ------- per-node aggregation + fused edge BN/silu/residual -----------------
__global__ void __launch_bounds__(256) node_agg(
    const int* __restrict__ starts, const int* __restrict__ elist,
    const int* __restrict__ ej, const __half* __restrict__ emsg,
    const __half* __restrict__ P,
    float* __restrict__ h, int nN, double* __restrict__ stats,
    const float* __restrict__ scaleE, const float* __restrict__ shiftE,
    const float* __restrict__ eres, float* __restrict__ eout)
{
    __shared__ float ssum[128], ssq[128];
    if (threadIdx.x < 128) { ssum[threadIdx.x] = 0.f; ssq[threadIdx.x] = 0.f; }
    __syncthreads();
    const int lane  = threadIdx.x & 31;
    const int warp  = (blockIdx.x * blockDim.x + threadIdx.x) >> 5;
    const int nwarp = (gridDim.x * blockDim.x) >> 5;
    const float4 scE = ((const float4*)scaleE)[lane];
    const float4 shE = ((const float4*)shiftE)[lane];
    const uint2* Eu = (const uint2*)emsg;   // row stride 32 uint2
    const uint2* Pu = (const uint2*)P;      // row stride 128 uint2
    float4 ls = make_float4(0.f, 0.f, 0.f, 0.f);
    float4 lq = make_float4(0.f, 0.f, 0.f, 0.f);
    for (int n = warp; n < nN; n += nwarp) {
        int s = starts[n], t = starts[n + 1];
        float4 sg = make_float4(0.f, 0.f, 0.f, 0.f);
        float4 sn = make_float4(0.f, 0.f, 0.f, 0.f);
        for (int k = s; k < t; k++) {
            int e = elist[k];
            int j = ej[e];
            float4 v  = h4_to_f4(__ldg(Eu + (size_t)e * 32 + lane));
            float4 sig = make_float4(sigm(v.x), sigm(v.y), sigm(v.z), sigm(v.w));
            float4 p4 = h4_to_f4(__ldg(Pu + (size_t)j * 128 + 96 + lane));
            sg.x += sig.x; sg.y += sig.y; sg.z += sig.z; sg.w += sig.w;
            sn.x += sig.x * p4.x; sn.y += sig.y * p4.y;
            sn.z += sig.z * p4.z; sn.w += sig.w * p4.w;
            // fused edge update: eout = silu(bn(v)) + eres
            float4 b = make_float4(v.x * scE.x + shE.x, v.y * scE.y + shE.y,
                                   v.z * scE.z + shE.z, v.w * scE.w + shE.w);
            float4 er = ((const float4*)eres)[(long long)e * 32 + lane];
            float4 eo = make_float4(b.x * sigm(b.x) + er.x, b.y * sigm(b.y) + er.y,
                                    b.z * sigm(b.z) + er.z, b.w * sigm(b.w) + er.w);
            ((float4*)eout)[(long long)e * 32 + lane] = eo;
        }
        float4 hv = h4_to_f4(__ldg(Pu + (size_t)n * 128 + 64 + lane));
        hv.x += sn.x / (sg.x + 1e-9f); hv.y += sn.y / (sg.y + 1e-9f);
        hv.z += sn.z / (sg.z + 1e-9f); hv.w += sn.w / (sg.w + 1e-9f);
        ((float4*)h)[(long long)n * 32 + lane] = hv;
        ls.x += hv.x; ls.y += hv.y; ls.z += hv.z; ls.w += hv.w;
        lq.x += hv.x * hv.x; lq.y += hv.y * hv.y;
        lq.z += hv.z * hv.z; lq.w += hv.w * hv.w;
    }
    atomicAdd(&ssum[lane * 4 + 0], ls.x); atomicAdd(&ssum[lane * 4 + 1], ls.y);
    atomicAdd(&ssum[lane * 4 + 2], ls.z); atomicAdd(&ssum[lane * 4 + 3], ls.w);
    atomicAdd(&ssq[lane * 4 + 0], lq.x);  atomicAdd(&ssq[lane * 4 + 1], lq.y);
    atomicAdd(&ssq[lane * 4 + 2], lq.z);  atomicAdd(&ssq[lane * 4 + 3], lq.w);
    __syncthreads();
    if (threadIdx.x < 128) {
        atomicAdd(&stats[threadIdx.x],       (double)ssum[threadIdx.x]);
        atomicAdd(&stats[128 + threadIdx.x], (double)ssq[threadIdx.x]);
    }
}

// ---------------- BN finalize + fused apply ---------------------------------
__global__ void finalize_bn(const double* __restrict__ stats,
                            const float* __restrict__ gamma,
                            const float* __restrict__ beta,
                            double invR, float* __restrict__ scale,
                            float* __restrict__ shift)
{
    int f = threadIdx.x;
    double mu  = stats[f] * invR;
    double var = stats[128 + f] * invR - mu * mu;
    float inv = rsqrtf((float)var + 1e-5f);
    float s = gamma[f] * inv;
    scale[f] = s;
    shift[f] = beta[f] - s * (float)mu;
}

__global__ void apply_bn_silu_res(const float* __restrict__ hbuf,
                                  const float* __restrict__ res,
                                  const float* __restrict__ scale,
                                  const float* __restrict__ shift,
                                  float* __restrict__ out, long long n4)
{
    for (long long idx = (long long)blockIdx.x * blockDim.x + threadIdx.x;
         idx < n4; idx += (long long)gridDim.x * blockDim.x) {
        int l = (int)(idx & 31);
        float4 sc = ((const float4*)scale)[l];
        float4 sh = ((const float4*)shift)[l];
        float4 v = ((const float4*)hbuf)[idx];
        v.x = v.x * sc.x + sh.x; v.y = v.y * sc.y + sh.y;
        v.z = v.z * sc.z + sh.z; v.w = v.w * sc.w + sh.w;
        float4 u = make_float4(v.x * sigm(v.x), v.y * sigm(v.y),
                               v.z * sigm(v.z), v.w * sigm(v.w));
        float4 r = ((const float4*)res)[idx];
        u.x += r.x; u.y += r.y; u.z += r.z; u.w += r.w;
        ((float4*)out)[idx] = u;
    }
}

// ---------------- host orchestration ----------------------------------------
struct Scratch {
    __half *P, *emsg;
    float *h;
    int *deg, *starts, *cursor, *elist, *bsum;
    double *statsE, *statsN;
    float *scaleE, *shiftE, *scaleN, *shiftN;
    __half *Whi, *Wlo;
    float *biasR;
};

static void run_conv(const Scratch& S, int conv,
                     const int* ei, const int* ej, int nN, int E,
                     const float* xnode, const float* eedge,
                     const float* bng, const float* bnb,
                     const float* node_res, float* node_out,
                     const float* edge_res, float* edge_out)
{
    cudaStream_t st = 0;
    cudaMemsetAsync(S.deg, 0, (size_t)nN * sizeof(int), st);
    cudaMemsetAsync(S.cursor, 0, (size_t)nN * sizeof(int), st);
    cudaMemsetAsync(S.statsE, 0, 256 * sizeof(double), st);
    cudaMemsetAsync(S.statsN, 0, 256 * sizeof(double), st);

    int gbN = (nN + 63) / 64;
    int gbE = (E + 63) / 64;
    const __half* Whi = S.Whi + (size_t)conv * 5 * 16384;
    const __half* Wlo = S.Wlo + (size_t)conv * 5 * 16384;
    const float* biasR = S.biasR + conv * 5 * 128;

    // CSR (independent)
    hist_deg<<<2048, 256, 0, st>>>(ei, S.deg, E);
    int nb = (nN + 1023) / 1024;
    scan1<<<nb, 1024, 0, st>>>(S.deg, S.starts, S.bsum, nN);
    scan2<<<1, 1024, 0, st>>>(S.bsum, nb);
    scan3<<<nb, 1024, 0, st>>>(S.starts, S.bsum, nN, E);
    scatter_edges<<<2048, 256, 0, st>>>(ei, S.starts, S.cursor, S.elist, E);

    // fused node projections (slots 0..3 -> P, fp16)
    gemm_mma<<<gbN, 256, GEMM_SMEM, st>>>(xnode, nN, Whi, Wlo, biasR, 4,
                                          S.P, 512, nullptr, nullptr, nullptr,
                                          nullptr);
    // edge projection + phase-2 fused gather-add + BN stats -> emsg (fp16)
    gemm_mma<<<gbE, 256, GEMM_SMEM, st>>>(eedge, E, Whi + 4 * 16384, Wlo + 4 * 16384,
                                          biasR + 4 * 128, 1, S.emsg, 128,
                                          ei, ej, S.P, S.statsE);
    finalize_bn<<<1, 128, 0, st>>>(S.statsE, bng + 0 * 128, bnb + 0 * 128,
                                   1.0 / (double)E, S.scaleE, S.shiftE);

    // node aggregation + node BN stats + fused edge BN/silu/residual output
    node_agg<<<4096, 256, 0, st>>>(S.starts, S.elist, ej, S.emsg, S.P,
                                   S.h, nN, S.statsN,
                                   S.scaleE, S.shiftE, edge_res, edge_out);
    finalize_bn<<<1, 128, 0, st>>>(S.statsN, bng + 1 * 128, bnb + 1 * 128,
                                   1.0 / (double)nN, S.scaleN, S.shiftN);

    long long n4n = (long long)nN * 32;
    int gbA = (int)((n4n + 255) / 256); if (gbA > 8192) gbA = 8192;
    apply_bn_silu_res<<<gbA, 256, 0, st>>>(S.h, node_res, S.scaleN, S.shiftN,
                                           node_out, n4n);
}

extern "C" void kernel_launch(void* const* d_in, const int* in_sizes, int n_in,
                              void* d_out, int out_size)
{
    const int*   gidx = (const int*)d_in[0];
    const int*   lidx = (const int*)d_in[1];
    const float* x    = (const float*)d_in[2];
    const float* y    = (const float*)d_in[3];
    const float* z    = (const float*)d_in[4];
    const float* W1   = (const float*)d_in[5];
    const float* b1   = (const float*)d_in[6];
    const float* bng1 = (const float*)d_in[7];
    const float* bnb1 = (const float*)d_in[8];
    const float* W2   = (const float*)d_in[9];
    const float* b2   = (const float*)d_in[10];
    const float* bng2 = (const float*)d_in[11];
    const float* bnb2 = (const float*)d_in[12];

    float* xo = (float*)d_out;
    float* yo = xo + (long long)NN1 * F;
    float* zo = yo + (long long)NE1 * F;

    Scratch S;
    cudaGetSymbolAddress((void**)&S.P, g_P);
    cudaGetSymbolAddress((void**)&S.emsg, g_emsg);
    cudaGetSymbolAddress((void**)&S.h, g_h);
    cudaGetSymbolAddress((void**)&S.deg, g_deg);
    cudaGetSymbolAddress((void**)&S.starts, g_starts);
    cudaGetSymbolAddress((void**)&S.cursor, g_cursor);
    cudaGetSymbolAddress((void**)&S.elist, g_elist);
    cudaGetSymbolAddress((void**)&S.bsum, g_bsum);
    cudaGetSymbolAddress((void**)&S.statsE, g_statsE);
    cudaGetSymbolAddress((void**)&S.statsN, g_statsN);
    cudaGetSymbolAddress((void**)&S.scaleE, g_scaleE);
    cudaGetSymbolAddress((void**)&S.shiftE, g_shiftE);
    cudaGetSymbolAddress((void**)&S.scaleN, g_scaleN);
    cudaGetSymbolAddress((void**)&S.shiftN, g_shiftN);
    cudaGetSymbolAddress((void**)&S.Whi, g_Whi);
    cudaGetSymbolAddress((void**)&S.Wlo, g_Wlo);
    cudaGetSymbolAddress((void**)&S.biasR, g_biasR);

    cudaFuncSetAttribute(gemm_mma, cudaFuncAttributeMaxDynamicSharedMemorySize,
                         GEMM_SMEM);

    prep_weights<<<(2 * 5 * 16384 + 255) / 256, 256>>>(W1, b1, W2, b2,
                                                       S.Whi, S.Wlo, S.biasR);

    // conv1: node_update on g
    run_conv(S, 0, gidx, gidx + NE1, NN1, NE1, x, y, bng1, bnb1,
             /*node_res=*/x, /*node_out=*/xo, /*edge_res=*/y, /*edge_out=*/yo);
    // conv2: edge_update on line graph (nodes = m = yo, edges = z)
    run_conv(S, 1, lidx, lidx + NE2, NE1, NE2, yo, z, bng2, bnb2,
             /*node_res=*/yo, /*node_out=*/yo, /*edge_res=*/z, /*edge_out=*/zo);
}